// round 7
// baseline (speedup 1.0000x reference)
#include <cuda_runtime.h>
#include <cuda_bf16.h>
#include <cstdint>

#define B_ 2
#define T_ 2048
#define D_ 1024
#define H_ 16
#define DK_ 64
#define M_ (B_*T_)
#define SCALE_ 0.125f

// ---------------- scratch ----------------
__device__ float g_Q[M_*D_];
__device__ float g_K[M_*D_];
__device__ float g_V[M_*D_];
__device__ float g_CTX[M_*D_];
__device__ float g_bias[M_];
__device__ int   g_maskmode;

// ---------------- mask dtype detection ----------------
__global__ void detect_mask_kernel(const unsigned int* __restrict__ w) {
    __shared__ int s_badint, s_badfloat;
    if (threadIdx.x == 0) { s_badint = 0; s_badfloat = 0; }
    __syncthreads();
    int bi = 0, bf = 0;
    for (int i = threadIdx.x; i < 1024; i += blockDim.x) {
        unsigned v = w[i];
        if (v > 1u) bi = 1;
        if (v != 0u && v != 0x3F800000u) bf = 1;
    }
    if (bi) atomicOr(&s_badint, 1);
    if (bf) atomicOr(&s_badfloat, 1);
    __syncthreads();
    if (threadIdx.x == 0)
        g_maskmode = (!s_badint) ? 0 : ((!s_badfloat) ? 1 : 2);
}

__global__ void build_bias_kernel(const void* __restrict__ mask) {
    int i = blockIdx.x * blockDim.x + threadIdx.x;
    if (i >= M_) return;
    int mode = g_maskmode;
    bool keep;
    if (mode == 0)      keep = ((const int*)mask)[i] != 0;
    else if (mode == 1) keep = ((const float*)mask)[i] != 0.0f;
    else                keep = ((const unsigned char*)mask)[i] != 0;
    g_bias[i] = keep ? 0.0f : -1e30f;
}

// ---------------- mma / ldmatrix helpers ----------------
__device__ __forceinline__ void mma_tf32(float* d, const uint32_t* a, const uint32_t* b) {
    asm volatile(
        "mma.sync.aligned.m16n8k8.row.col.f32.tf32.tf32.f32 "
        "{%0,%1,%2,%3}, {%4,%5,%6,%7}, {%8,%9}, {%0,%1,%2,%3};"
        : "+f"(d[0]), "+f"(d[1]), "+f"(d[2]), "+f"(d[3])
        : "r"(a[0]), "r"(a[1]), "r"(a[2]), "r"(a[3]), "r"(b[0]), "r"(b[1]));
}

__device__ __forceinline__ void mma_bf16(float* d, const uint32_t* a, const uint32_t* b) {
    asm volatile(
        "mma.sync.aligned.m16n8k16.row.col.f32.bf16.bf16.f32 "
        "{%0,%1,%2,%3}, {%4,%5,%6,%7}, {%8,%9}, {%0,%1,%2,%3};"
        : "+f"(d[0]), "+f"(d[1]), "+f"(d[2]), "+f"(d[3])
        : "r"(a[0]), "r"(a[1]), "r"(a[2]), "r"(a[3]), "r"(b[0]), "r"(b[1]));
}

__device__ __forceinline__ void ldsm4(uint32_t& r0, uint32_t& r1, uint32_t& r2, uint32_t& r3,
                                      uint32_t saddr) {
    asm volatile("ldmatrix.sync.aligned.m8n8.x4.shared.b16 {%0,%1,%2,%3}, [%4];"
                 : "=r"(r0), "=r"(r1), "=r"(r2), "=r"(r3) : "r"(saddr));
}

__device__ __forceinline__ uint32_t f2tf32(float x) {
    uint32_t r;
    asm("cvt.rna.tf32.f32 %0, %1;" : "=r"(r) : "f"(x));
    return r;
}

__device__ __forceinline__ void split_bf(float x, float& h, float& l) {
    h = __bfloat162float(__float2bfloat16(x));
    l = x - h;
}

__device__ __forceinline__ uint32_t packbf(float a, float b) {
    __nv_bfloat162 t = __floats2bfloat162_rn(a, b);
    return *reinterpret_cast<uint32_t*>(&t);
}

__device__ __forceinline__ uint32_t smem_u32(const void* p) {
    return (uint32_t)__cvta_generic_to_shared(p);
}

// ================= bf16x3 GEMM with ldmatrix fragment loads ==================
// C[M,N] = A[M,K] @ W[N,K]^T + b. Block 64x128, 8 warps (2m x 4n), k-step 16.
// Stride 12 words = 48B: rows 16B-aligned, (12r mod 32)+4c conflict-free.
#define GST 12

__global__ __launch_bounds__(256) void gemm_bf16x3_kernel(
    const float* __restrict__ A, const float* __restrict__ W,
    const float* __restrict__ bvec, float* __restrict__ C)
{
    __shared__ __align__(16) uint32_t Ahs[2][64 * GST];
    __shared__ __align__(16) uint32_t Als[2][64 * GST];
    __shared__ __align__(16) uint32_t Bhs[2][128 * GST];
    __shared__ __align__(16) uint32_t Bls[2][128 * GST];

    const int tid  = threadIdx.x;
    const int lane = tid & 31, wid = tid >> 5;
    const int wm   = (wid >> 2) * 32;
    const int wn   = (wid & 3) * 32;
    const int gid  = lane >> 2, tig = lane & 3;
    const int m0 = blockIdx.y * 64;
    const int n0 = blockIdx.x * 128;

    float acc[2][4][4];
#pragma unroll
    for (int mt = 0; mt < 2; mt++)
#pragma unroll
        for (int nt = 0; nt < 4; nt++)
#pragma unroll
            for (int i = 0; i < 4; i++) acc[mt][nt][i] = 0.f;

    const int arow = tid >> 2;
    const int acg  = (tid & 3) * 4;
    const int pb2  = (tid & 3) * 2;
    const float* Ag  = A + (size_t)(m0 + arow) * 1024 + acg;
    const float* Wg0 = W + (size_t)(n0 + arow) * 1024 + acg;
    const float* Wg1 = W + (size_t)(n0 + arow + 64) * 1024 + acg;

    // ldmatrix per-lane offsets (bytes); every address 16B-aligned with GST=12
    const uint32_t aOff = ((lane & 15) * GST + (lane >> 4) * 4) * 4;
    const uint32_t bOff = ((((lane >> 4) * 8) + (lane & 7)) * GST + ((lane >> 3) & 1) * 4) * 4;

    const uint32_t sAh = smem_u32(Ahs), sAl = smem_u32(Als);
    const uint32_t sBh = smem_u32(Bhs), sBl = smem_u32(Bls);
    const uint32_t ABUF = 64 * GST * 4, BBUF = 128 * GST * 4;

    float4 pa, pw0, pw1;
    pa  = *(const float4*)(Ag);
    pw0 = *(const float4*)(Wg0);
    pw1 = *(const float4*)(Wg1);

#define GSTORE(BUF)                                                           \
    do {                                                                      \
        float h0,h1,h2,h3,l0,l1,l2,l3;                                        \
        split_bf(pa.x,h0,l0); split_bf(pa.y,h1,l1);                           \
        split_bf(pa.z,h2,l2); split_bf(pa.w,h3,l3);                           \
        *(uint2*)&Ahs[BUF][arow*GST+pb2] = make_uint2(packbf(h0,h1),packbf(h2,h3)); \
        *(uint2*)&Als[BUF][arow*GST+pb2] = make_uint2(packbf(l0,l1),packbf(l2,l3)); \
        split_bf(pw0.x,h0,l0); split_bf(pw0.y,h1,l1);                         \
        split_bf(pw0.z,h2,l2); split_bf(pw0.w,h3,l3);                         \
        *(uint2*)&Bhs[BUF][arow*GST+pb2] = make_uint2(packbf(h0,h1),packbf(h2,h3)); \
        *(uint2*)&Bls[BUF][arow*GST+pb2] = make_uint2(packbf(l0,l1),packbf(l2,l3)); \
        split_bf(pw1.x,h0,l0); split_bf(pw1.y,h1,l1);                         \
        split_bf(pw1.z,h2,l2); split_bf(pw1.w,h3,l3);                         \
        *(uint2*)&Bhs[BUF][(arow+64)*GST+pb2] = make_uint2(packbf(h0,h1),packbf(h2,h3)); \
        *(uint2*)&Bls[BUF][(arow+64)*GST+pb2] = make_uint2(packbf(l0,l1),packbf(l2,l3)); \
    } while (0)

#define GCOMP(BUF)                                                           \
    do {                                                                     \
        uint32_t a_h[2][4], a_l[2][4], b_h[4][2], b_l[4][2];                 \
        _Pragma("unroll")                                                    \
        for (int mt = 0; mt < 2; mt++) {                                     \
            uint32_t ro = (uint32_t)((wm + mt * 16) * GST * 4);              \
            ldsm4(a_h[mt][0], a_h[mt][1], a_h[mt][2], a_h[mt][3],            \
                  sAh + (BUF) * ABUF + ro + aOff);                           \
            ldsm4(a_l[mt][0], a_l[mt][1], a_l[mt][2], a_l[mt][3],            \
                  sAl + (BUF) * ABUF + ro + aOff);                           \
        }                                                                    \
        _Pragma("unroll")                                                    \
        for (int ntp = 0; ntp < 2; ntp++) {                                  \
            uint32_t ro = (uint32_t)((wn + ntp * 16) * GST * 4);             \
            ldsm4(b_h[2*ntp][0], b_h[2*ntp][1], b_h[2*ntp+1][0], b_h[2*ntp+1][1], \
                  sBh + (BUF) * BBUF + ro + bOff);                           \
            ldsm4(b_l[2*ntp][0], b_l[2*ntp][1], b_l[2*ntp+1][0], b_l[2*ntp+1][1], \
                  sBl + (BUF) * BBUF + ro + bOff);                           \
        }                                                                    \
        _Pragma("unroll")                                                    \
        for (int mt = 0; mt < 2; mt++)                                       \
            _Pragma("unroll")                                                \
            for (int nt = 0; nt < 4; nt++) {                                 \
                mma_bf16(acc[mt][nt], a_h[mt], b_h[nt]);                     \
                mma_bf16(acc[mt][nt], a_l[mt], b_h[nt]);                     \
                mma_bf16(acc[mt][nt], a_h[mt], b_l[nt]);                     \
            }                                                                \
    } while (0)

    GSTORE(0);
    __syncthreads();

    int buf = 0;
    for (int k0 = 16; k0 < 1024; k0 += 16) {
        pa  = *(const float4*)(Ag + k0);
        pw0 = *(const float4*)(Wg0 + k0);
        pw1 = *(const float4*)(Wg1 + k0);
        if (buf == 0) GCOMP(0); else GCOMP(1);
        __syncthreads();
        if (buf == 0) GSTORE(1); else GSTORE(0);
        __syncthreads();
        buf ^= 1;
    }
    if (buf == 0) GCOMP(0); else GCOMP(1);

#pragma unroll
    for (int mt = 0; mt < 2; mt++) {
#pragma unroll
        for (int nt = 0; nt < 4; nt++) {
            int gm = m0 + wm + mt * 16 + gid;
            int gn = n0 + wn + nt * 8 + tig * 2;
            float b0 = __ldg(bvec + gn);
            float b1 = __ldg(bvec + gn + 1);
            *(float2*)&C[(size_t)gm * 1024 + gn] =
                make_float2(acc[mt][nt][0] + b0, acc[mt][nt][1] + b1);
            *(float2*)&C[(size_t)(gm + 8) * 1024 + gn] =
                make_float2(acc[mt][nt][2] + b0, acc[mt][nt][3] + b1);
        }
    }
}

// ================= tensor-core flash attention ==================
// QK^T: tf32 x1, K smem pair-permuted (LDS.64 frag loads).
// P*V: bf16 x3, V transposed planes + P planes loaded via ldmatrix.
#define KPAD 68
#define VSTR 20   // 80B stride: 16B-aligned, (20r mod 32) conflict-free
#define PSTR 20

__global__ __launch_bounds__(256) void attn_mma_kernel(
    const float* __restrict__ Qg, const float* __restrict__ Kg,
    const float* __restrict__ Vg, float* __restrict__ CTX)
{
    __shared__ __align__(16) float    Ks[32 * KPAD];
    __shared__ __align__(16) uint32_t Vh[64 * VSTR];
    __shared__ __align__(16) uint32_t Vl[64 * VSTR];
    __shared__ __align__(16) uint32_t Ph[8][16 * PSTR];
    __shared__ __align__(16) uint32_t Pl[8][16 * PSTR];
    __shared__ float    Bs[32];

    const int tid  = threadIdx.x;
    const int lane = tid & 31, wid = tid >> 5;
    const int gid  = lane >> 2, tig = lane & 3;
    const int b = blockIdx.z, h = blockIdx.y;
    const int t0 = blockIdx.x * 128;

    const size_t kvBase = ((size_t)b * T_) * D_ + h * DK_;

    // Q fragments: tf32-rounded registers
    uint32_t Qr[8][4];
    {
        const int r0 = t0 + wid * 16 + gid;
        const float* q0 = Qg + ((size_t)(b * T_) + r0) * D_ + h * DK_;
        const float* q1 = q0 + 8 * D_;
#pragma unroll
        for (int ks = 0; ks < 8; ks++) {
            int c = ks * 8 + tig;
            Qr[ks][0] = f2tf32(q0[c]);
            Qr[ks][1] = f2tf32(q1[c]);
            Qr[ks][2] = f2tf32(q0[c + 4]);
            Qr[ks][3] = f2tf32(q1[c + 4]);
        }
    }

    float oacc[8][4];
#pragma unroll
    for (int nt = 0; nt < 8; nt++)
#pragma unroll
        for (int i = 0; i < 4; i++) oacc[nt][i] = 0.f;
    float m0 = -1e30f, m1 = -1e30f, l0 = 0.f, l1 = 0.f;

    // fill mappings + prefetch
    const int frow = tid >> 4;
    const int fc4  = (tid & 15) * 4;
    const float* kRow = Kg + kvBase + (size_t)frow * D_ + fc4;

    const int vp  = tid >> 4;             // V k-pair 0..15
    const int vcg = (tid & 15) * 4;       // d base
    const float* vRow0 = Vg + kvBase + (size_t)(2 * vp) * D_ + vcg;
    const float* vRow1 = vRow0 + D_;

    // permuted K positions: k (mod 8) p -> (p&3)*2 + (p>>2)
    int kpos[4];
#pragma unroll
    for (int j = 0; j < 4; j++) {
        int k = fc4 + j, p = k & 7;
        kpos[j] = (k >> 3) * 8 + ((p & 3) * 2 + (p >> 2));
    }

    // ldmatrix lane offsets (all 16B-aligned: strides 20 words = 80B)
    const uint32_t pOff = ((lane & 15) * PSTR + (lane >> 4) * 4) * 4;
    const uint32_t vOff = ((((lane >> 4) * 8) + (lane & 7)) * VSTR + ((lane >> 3) & 1) * 4) * 4;
    const uint32_t sPh = smem_u32(Ph[wid]), sPl = smem_u32(Pl[wid]);
    const uint32_t sVh = smem_u32(Vh), sVl = smem_u32(Vl);

    float4 ka  = *(const float4*)(kRow);
    float4 kb4 = *(const float4*)(kRow + 16 * D_);
    float4 va0 = *(const float4*)(vRow0);
    float4 va1 = *(const float4*)(vRow1);

    for (int s0 = 0; s0 < T_; s0 += 32) {
        __syncthreads();
        {
            float* kd0 = &Ks[frow * KPAD];
            kd0[kpos[0]] = __uint_as_float(f2tf32(ka.x));
            kd0[kpos[1]] = __uint_as_float(f2tf32(ka.y));
            kd0[kpos[2]] = __uint_as_float(f2tf32(ka.z));
            kd0[kpos[3]] = __uint_as_float(f2tf32(ka.w));
            float* kd1 = &Ks[(frow + 16) * KPAD];
            kd1[kpos[0]] = __uint_as_float(f2tf32(kb4.x));
            kd1[kpos[1]] = __uint_as_float(f2tf32(kb4.y));
            kd1[kpos[2]] = __uint_as_float(f2tf32(kb4.z));
            kd1[kpos[3]] = __uint_as_float(f2tf32(kb4.w));

            float h0, lo0, h1, lo1;
            split_bf(va0.x, h0, lo0); split_bf(va1.x, h1, lo1);
            Vh[(vcg + 0) * VSTR + vp] = packbf(h0, h1);
            Vl[(vcg + 0) * VSTR + vp] = packbf(lo0, lo1);
            split_bf(va0.y, h0, lo0); split_bf(va1.y, h1, lo1);
            Vh[(vcg + 1) * VSTR + vp] = packbf(h0, h1);
            Vl[(vcg + 1) * VSTR + vp] = packbf(lo0, lo1);
            split_bf(va0.z, h0, lo0); split_bf(va1.z, h1, lo1);
            Vh[(vcg + 2) * VSTR + vp] = packbf(h0, h1);
            Vl[(vcg + 2) * VSTR + vp] = packbf(lo0, lo1);
            split_bf(va0.w, h0, lo0); split_bf(va1.w, h1, lo1);
            Vh[(vcg + 3) * VSTR + vp] = packbf(h0, h1);
            Vl[(vcg + 3) * VSTR + vp] = packbf(lo0, lo1);

            if (tid < 32) Bs[tid] = g_bias[b * T_ + s0 + tid];
        }
        __syncthreads();

        if (s0 + 32 < T_) {
            ka  = *(const float4*)(kRow + (size_t)(s0 + 32) * D_);
            kb4 = *(const float4*)(kRow + (size_t)(s0 + 48) * D_);
            va0 = *(const float4*)(vRow0 + (size_t)(s0 + 32) * D_);
            va1 = *(const float4*)(vRow1 + (size_t)(s0 + 32) * D_);
        }

        // ---- S = Q K^T (tf32 x1), LDS.64 B-frags ----
        float sacc[4][4];
#pragma unroll
        for (int nt = 0; nt < 4; nt++)
#pragma unroll
            for (int i = 0; i < 4; i++) sacc[nt][i] = 0.f;
#pragma unroll
        for (int ks = 0; ks < 8; ks++) {
#pragma unroll
            for (int nt = 0; nt < 4; nt++) {
                float2 kv = *(const float2*)&Ks[(nt * 8 + gid) * KPAD + ks * 8 + tig * 2];
                uint32_t bf[2];
                bf[0] = __float_as_uint(kv.x);
                bf[1] = __float_as_uint(kv.y);
                mma_tf32(sacc[nt], Qr[ks], bf);
            }
        }

        // ---- scale + bias, online softmax ----
        float sv[4][4];
#pragma unroll
        for (int nt = 0; nt < 4; nt++) {
            int c0 = nt * 8 + 2 * tig;
            float bb0 = Bs[c0], bb1 = Bs[c0 + 1];
            sv[nt][0] = sacc[nt][0] * SCALE_ + bb0;
            sv[nt][1] = sacc[nt][1] * SCALE_ + bb1;
            sv[nt][2] = sacc[nt][2] * SCALE_ + bb0;
            sv[nt][3] = sacc[nt][3] * SCALE_ + bb1;
        }
        float mx0 = fmaxf(fmaxf(sv[0][0], sv[0][1]), fmaxf(sv[1][0], sv[1][1]));
        mx0 = fmaxf(mx0, fmaxf(fmaxf(sv[2][0], sv[2][1]), fmaxf(sv[3][0], sv[3][1])));
        float mx1 = fmaxf(fmaxf(sv[0][2], sv[0][3]), fmaxf(sv[1][2], sv[1][3]));
        mx1 = fmaxf(mx1, fmaxf(fmaxf(sv[2][2], sv[2][3]), fmaxf(sv[3][2], sv[3][3])));
        mx0 = fmaxf(mx0, __shfl_xor_sync(0xffffffffu, mx0, 1));
        mx0 = fmaxf(mx0, __shfl_xor_sync(0xffffffffu, mx0, 2));
        mx1 = fmaxf(mx1, __shfl_xor_sync(0xffffffffu, mx1, 1));
        mx1 = fmaxf(mx1, __shfl_xor_sync(0xffffffffu, mx1, 2));

        float m0n = fmaxf(m0, mx0), m1n = fmaxf(m1, mx1);
        float c0f = __expf(m0 - m0n), c1f = __expf(m1 - m1n);
        m0 = m0n; m1 = m1n;

        float rs0 = 0.f, rs1 = 0.f;
#pragma unroll
        for (int nt = 0; nt < 4; nt++) {
            float p0 = __expf(sv[nt][0] - m0n);
            float p1 = __expf(sv[nt][1] - m0n);
            float p2 = __expf(sv[nt][2] - m1n);
            float p3 = __expf(sv[nt][3] - m1n);
            rs0 += p0 + p1; rs1 += p2 + p3;
            float h0, lo0, h1, lo1;
            int pi = nt * 4 + tig;
            split_bf(p0, h0, lo0); split_bf(p1, h1, lo1);
            Ph[wid][gid * PSTR + pi] = packbf(h0, h1);
            Pl[wid][gid * PSTR + pi] = packbf(lo0, lo1);
            split_bf(p2, h0, lo0); split_bf(p3, h1, lo1);
            Ph[wid][(gid + 8) * PSTR + pi] = packbf(h0, h1);
            Pl[wid][(gid + 8) * PSTR + pi] = packbf(lo0, lo1);
        }
        rs0 += __shfl_xor_sync(0xffffffffu, rs0, 1);
        rs0 += __shfl_xor_sync(0xffffffffu, rs0, 2);
        rs1 += __shfl_xor_sync(0xffffffffu, rs1, 1);
        rs1 += __shfl_xor_sync(0xffffffffu, rs1, 2);
        l0 = l0 * c0f + rs0;
        l1 = l1 * c1f + rs1;
#pragma unroll
        for (int nt = 0; nt < 8; nt++) {
            oacc[nt][0] *= c0f; oacc[nt][1] *= c0f;
            oacc[nt][2] *= c1f; oacc[nt][3] *= c1f;
        }
        __syncwarp();

        // ---- O += P V (bf16 x3, ldmatrix frags) ----
#pragma unroll
        for (int kk = 0; kk < 2; kk++) {
            uint32_t ah[4], al[4];
            ldsm4(ah[0], ah[1], ah[2], ah[3], sPh + (uint32_t)(kk * 32) + pOff);
            ldsm4(al[0], al[1], al[2], al[3], sPl + (uint32_t)(kk * 32) + pOff);
#pragma unroll
            for (int n4 = 0; n4 < 4; n4++) {
                uint32_t bh[2][2], bl[2][2];
                uint32_t ro = (uint32_t)(n4 * 16 * VSTR * 4 + kk * 32);
                ldsm4(bh[0][0], bh[0][1], bh[1][0], bh[1][1], sVh + ro + vOff);
                ldsm4(bl[0][0], bl[0][1], bl[1][0], bl[1][1], sVl + ro + vOff);
#pragma unroll
                for (int half = 0; half < 2; half++) {
                    int nt = n4 * 2 + half;
                    mma_bf16(oacc[nt], ah, bh[half]);
                    mma_bf16(oacc[nt], al, bh[half]);
                    mma_bf16(oacc[nt], ah, bl[half]);
                }
            }
        }
        __syncwarp();
    }

    // ---- epilogue ----
    float inv0 = 1.f / l0, inv1 = 1.f / l1;
    const int gr0 = t0 + wid * 16 + gid;
    float* o0 = CTX + ((size_t)(b * T_) + gr0) * D_ + h * DK_;
    float* o1 = o0 + 8 * D_;
#pragma unroll
    for (int nt = 0; nt < 8; nt++) {
        int c = nt * 8 + 2 * tig;
        *(float2*)(o0 + c) = make_float2(oacc[nt][0] * inv0, oacc[nt][1] * inv0);
        *(float2*)(o1 + c) = make_float2(oacc[nt][2] * inv1, oacc[nt][3] * inv1);
    }
}

// ---------------- launch ----------------
extern "C" void kernel_launch(void* const* d_in, const int* in_sizes, int n_in,
                              void* d_out, int out_size)
{
    const float* query = (const float*)d_in[0];
    const float* key   = (const float*)d_in[1];
    const float* value = (const float*)d_in[2];
    const void*  mask  = d_in[3];
    const float* Wq = (const float*)d_in[4];  const float* bq = (const float*)d_in[5];
    const float* Wk = (const float*)d_in[6];  const float* bk = (const float*)d_in[7];
    const float* Wv = (const float*)d_in[8];  const float* bv = (const float*)d_in[9];
    const float* Wo = (const float*)d_in[10]; const float* bo = (const float*)d_in[11];

    float *Qb, *Kb, *Vb, *Cb;
    cudaGetSymbolAddress((void**)&Qb, g_Q);
    cudaGetSymbolAddress((void**)&Kb, g_K);
    cudaGetSymbolAddress((void**)&Vb, g_V);
    cudaGetSymbolAddress((void**)&Cb, g_CTX);

    detect_mask_kernel<<<1, 256>>>((const unsigned int*)mask);
    build_bias_kernel<<<(M_ + 255) / 256, 256>>>(mask);

    dim3 gg(D_ / 128, M_ / 64);   // (8, 64)
    gemm_bf16x3_kernel<<<gg, 256>>>(query, Wq, bq, Qb);
    gemm_bf16x3_kernel<<<gg, 256>>>(key,   Wk, bk, Kb);
    gemm_bf16x3_kernel<<<gg, 256>>>(value, Wv, bv, Vb);

    attn_mma_kernel<<<dim3(T_ / 128, H_, B_), 256>>>(Qb, Kb, Vb, Cb);

    gemm_bf16x3_kernel<<<gg, 256>>>(Cb, Wo, bo, (float*)d_out);
}

// round 8
// speedup vs baseline: 1.1631x; 1.1631x over previous
#include <cuda_runtime.h>
#include <cuda_bf16.h>
#include <cstdint>

#define B_ 2
#define T_ 2048
#define D_ 1024
#define H_ 16
#define DK_ 64
#define M_ (B_*T_)
#define SCALE_ 0.125f

// ---------------- scratch ----------------
__device__ float g_Q[M_*D_];
__device__ float g_K[M_*D_];
__device__ float g_V[M_*D_];
__device__ float g_CTX[M_*D_];
__device__ float g_bias[M_];
__device__ int   g_maskmode;

// ---------------- mask dtype detection ----------------
__global__ void detect_mask_kernel(const unsigned int* __restrict__ w) {
    __shared__ int s_badint, s_badfloat;
    if (threadIdx.x == 0) { s_badint = 0; s_badfloat = 0; }
    __syncthreads();
    int bi = 0, bf = 0;
    for (int i = threadIdx.x; i < 1024; i += blockDim.x) {
        unsigned v = w[i];
        if (v > 1u) bi = 1;
        if (v != 0u && v != 0x3F800000u) bf = 1;
    }
    if (bi) atomicOr(&s_badint, 1);
    if (bf) atomicOr(&s_badfloat, 1);
    __syncthreads();
    if (threadIdx.x == 0)
        g_maskmode = (!s_badint) ? 0 : ((!s_badfloat) ? 1 : 2);
}

__global__ void build_bias_kernel(const void* __restrict__ mask) {
    int i = blockIdx.x * blockDim.x + threadIdx.x;
    if (i >= M_) return;
    int mode = g_maskmode;
    bool keep;
    if (mode == 0)      keep = ((const int*)mask)[i] != 0;
    else if (mode == 1) keep = ((const float*)mask)[i] != 0.0f;
    else                keep = ((const unsigned char*)mask)[i] != 0;
    g_bias[i] = keep ? 0.0f : -1e30f;
}

// ---------------- mma / ldmatrix helpers ----------------
__device__ __forceinline__ void mma_tf32(float* d, const uint32_t* a, const uint32_t* b) {
    asm volatile(
        "mma.sync.aligned.m16n8k8.row.col.f32.tf32.tf32.f32 "
        "{%0,%1,%2,%3}, {%4,%5,%6,%7}, {%8,%9}, {%0,%1,%2,%3};"
        : "+f"(d[0]), "+f"(d[1]), "+f"(d[2]), "+f"(d[3])
        : "r"(a[0]), "r"(a[1]), "r"(a[2]), "r"(a[3]), "r"(b[0]), "r"(b[1]));
}

__device__ __forceinline__ void mma_bf16(float* d, const uint32_t* a, const uint32_t* b) {
    asm volatile(
        "mma.sync.aligned.m16n8k16.row.col.f32.bf16.bf16.f32 "
        "{%0,%1,%2,%3}, {%4,%5,%6,%7}, {%8,%9}, {%0,%1,%2,%3};"
        : "+f"(d[0]), "+f"(d[1]), "+f"(d[2]), "+f"(d[3])
        : "r"(a[0]), "r"(a[1]), "r"(a[2]), "r"(a[3]), "r"(b[0]), "r"(b[1]));
}

__device__ __forceinline__ void ldsm4(uint32_t& r0, uint32_t& r1, uint32_t& r2, uint32_t& r3,
                                      uint32_t saddr) {
    asm volatile("ldmatrix.sync.aligned.m8n8.x4.shared.b16 {%0,%1,%2,%3}, [%4];"
                 : "=r"(r0), "=r"(r1), "=r"(r2), "=r"(r3) : "r"(saddr));
}

__device__ __forceinline__ uint32_t f2tf32(float x) {
    uint32_t r;
    asm("cvt.rna.tf32.f32 %0, %1;" : "=r"(r) : "f"(x));
    return r;
}

__device__ __forceinline__ void split_bf(float x, float& h, float& l) {
    h = __bfloat162float(__float2bfloat16(x));
    l = x - h;
}

__device__ __forceinline__ uint32_t packbf(float a, float b) {
    __nv_bfloat162 t = __floats2bfloat162_rn(a, b);
    return *reinterpret_cast<uint32_t*>(&t);
}

__device__ __forceinline__ uint32_t smem_u32(const void* p) {
    return (uint32_t)__cvta_generic_to_shared(p);
}

// ================= bf16x3 GEMM, 128x128 tile, ldmatrix frags ==================
// C[M,N] = A[M,K] @ W[N,K]^T + b. 8 warps (2m x 4n), warp tile 64x32, k-step 16.
#define GST 12

__global__ __launch_bounds__(256, 2) void gemm_bf16x3_kernel(
    const float* __restrict__ A, const float* __restrict__ W,
    const float* __restrict__ bvec, float* __restrict__ C)
{
    __shared__ __align__(16) uint32_t Ahs[2][128 * GST];
    __shared__ __align__(16) uint32_t Als[2][128 * GST];
    __shared__ __align__(16) uint32_t Bhs[2][128 * GST];
    __shared__ __align__(16) uint32_t Bls[2][128 * GST];

    const int tid  = threadIdx.x;
    const int lane = tid & 31, wid = tid >> 5;
    const int wm   = (wid >> 2) * 64;     // 0 / 64
    const int wn   = (wid & 3) * 32;      // 0..96
    const int gid  = lane >> 2, tig = lane & 3;
    const int m0 = blockIdx.y * 128;
    const int n0 = blockIdx.x * 128;

    float acc[4][4][4];
#pragma unroll
    for (int mt = 0; mt < 4; mt++)
#pragma unroll
        for (int nt = 0; nt < 4; nt++)
#pragma unroll
            for (int i = 0; i < 4; i++) acc[mt][nt][i] = 0.f;

    // fill mapping: 2 threads per row, 8 floats each
    const int frow = tid >> 1;            // 0..127
    const int kh   = tid & 1;             // k-half
    const float* Ag = A + (size_t)(m0 + frow) * 1024 + kh * 8;
    const float* Wg = W + (size_t)(n0 + frow) * 1024 + kh * 8;

    // ldmatrix per-lane offsets (bytes); 16B-aligned with GST=12
    const uint32_t aOff = ((lane & 15) * GST + (lane >> 4) * 4) * 4;
    const uint32_t bOff = ((((lane >> 4) * 8) + (lane & 7)) * GST + ((lane >> 3) & 1) * 4) * 4;

    const uint32_t sAh = smem_u32(Ahs), sAl = smem_u32(Als);
    const uint32_t sBh = smem_u32(Bhs), sBl = smem_u32(Bls);
    const uint32_t PBUF = 128 * GST * 4;

    float4 pa0, pa1, pw0, pw1;
    pa0 = *(const float4*)(Ag);
    pa1 = *(const float4*)(Ag + 4);
    pw0 = *(const float4*)(Wg);
    pw1 = *(const float4*)(Wg + 4);

#define GSTORE(BUF)                                                            \
    do {                                                                       \
        float h0,h1,h2,h3,h4,h5,h6,h7,l0,l1,l2,l3,l4,l5,l6,l7;                 \
        split_bf(pa0.x,h0,l0); split_bf(pa0.y,h1,l1);                          \
        split_bf(pa0.z,h2,l2); split_bf(pa0.w,h3,l3);                          \
        split_bf(pa1.x,h4,l4); split_bf(pa1.y,h5,l5);                          \
        split_bf(pa1.z,h6,l6); split_bf(pa1.w,h7,l7);                          \
        *(uint4*)&Ahs[BUF][frow*GST + kh*4] =                                  \
            make_uint4(packbf(h0,h1),packbf(h2,h3),packbf(h4,h5),packbf(h6,h7)); \
        *(uint4*)&Als[BUF][frow*GST + kh*4] =                                  \
            make_uint4(packbf(l0,l1),packbf(l2,l3),packbf(l4,l5),packbf(l6,l7)); \
        split_bf(pw0.x,h0,l0); split_bf(pw0.y,h1,l1);                          \
        split_bf(pw0.z,h2,l2); split_bf(pw0.w,h3,l3);                          \
        split_bf(pw1.x,h4,l4); split_bf(pw1.y,h5,l5);                          \
        split_bf(pw1.z,h6,l6); split_bf(pw1.w,h7,l7);                          \
        *(uint4*)&Bhs[BUF][frow*GST + kh*4] =                                  \
            make_uint4(packbf(h0,h1),packbf(h2,h3),packbf(h4,h5),packbf(h6,h7)); \
        *(uint4*)&Bls[BUF][frow*GST + kh*4] =                                  \
            make_uint4(packbf(l0,l1),packbf(l2,l3),packbf(l4,l5),packbf(l6,l7)); \
    } while (0)

#define GCOMP(BUF)                                                            \
    do {                                                                      \
        uint32_t a_h[4][4], a_l[4][4], b_h[4][2], b_l[4][2];                  \
        _Pragma("unroll")                                                     \
        for (int mt = 0; mt < 4; mt++) {                                      \
            uint32_t ro = (uint32_t)((wm + mt * 16) * GST * 4);               \
            ldsm4(a_h[mt][0], a_h[mt][1], a_h[mt][2], a_h[mt][3],             \
                  sAh + (BUF) * PBUF + ro + aOff);                            \
            ldsm4(a_l[mt][0], a_l[mt][1], a_l[mt][2], a_l[mt][3],             \
                  sAl + (BUF) * PBUF + ro + aOff);                            \
        }                                                                     \
        _Pragma("unroll")                                                     \
        for (int ntp = 0; ntp < 2; ntp++) {                                   \
            uint32_t ro = (uint32_t)((wn + ntp * 16) * GST * 4);              \
            ldsm4(b_h[2*ntp][0], b_h[2*ntp][1], b_h[2*ntp+1][0], b_h[2*ntp+1][1], \
                  sBh + (BUF) * PBUF + ro + bOff);                            \
            ldsm4(b_l[2*ntp][0], b_l[2*ntp][1], b_l[2*ntp+1][0], b_l[2*ntp+1][1], \
                  sBl + (BUF) * PBUF + ro + bOff);                            \
        }                                                                     \
        _Pragma("unroll")                                                     \
        for (int mt = 0; mt < 4; mt++)                                        \
            _Pragma("unroll")                                                 \
            for (int nt = 0; nt < 4; nt++) {                                  \
                mma_bf16(acc[mt][nt], a_h[mt], b_h[nt]);                      \
                mma_bf16(acc[mt][nt], a_l[mt], b_h[nt]);                      \
                mma_bf16(acc[mt][nt], a_h[mt], b_l[nt]);                      \
            }                                                                 \
    } while (0)

    GSTORE(0);
    __syncthreads();

    int buf = 0;
    for (int k0 = 16; k0 < 1024; k0 += 16) {
        pa0 = *(const float4*)(Ag + k0);
        pa1 = *(const float4*)(Ag + k0 + 4);
        pw0 = *(const float4*)(Wg + k0);
        pw1 = *(const float4*)(Wg + k0 + 4);
        if (buf == 0) GCOMP(0); else GCOMP(1);
        __syncthreads();
        if (buf == 0) GSTORE(1); else GSTORE(0);
        __syncthreads();
        buf ^= 1;
    }
    if (buf == 0) GCOMP(0); else GCOMP(1);

#pragma unroll
    for (int mt = 0; mt < 4; mt++) {
#pragma unroll
        for (int nt = 0; nt < 4; nt++) {
            int gm = m0 + wm + mt * 16 + gid;
            int gn = n0 + wn + nt * 8 + tig * 2;
            float b0 = __ldg(bvec + gn);
            float b1 = __ldg(bvec + gn + 1);
            *(float2*)&C[(size_t)gm * 1024 + gn] =
                make_float2(acc[mt][nt][0] + b0, acc[mt][nt][1] + b1);
            *(float2*)&C[(size_t)(gm + 8) * 1024 + gn] =
                make_float2(acc[mt][nt][2] + b0, acc[mt][nt][3] + b1);
        }
    }
}

// ================= tensor-core flash attention (R4 version) ==================
// QK^T: tf32 x1. P*V: bf16 x3 (m16n8k16), V and P pre-split packed bf16x2.
#define KPAD 68
#define AVSTR 72   // uint32 stride per k-pair row of V planes
#define PSTR 20    // uint32 stride per row of P planes

__global__ __launch_bounds__(256) void attn_mma_kernel(
    const float* __restrict__ Qg, const float* __restrict__ Kg,
    const float* __restrict__ Vg, float* __restrict__ CTX)
{
    __shared__ float    Ks[32 * KPAD];
    __shared__ uint32_t Vh[16 * AVSTR];
    __shared__ uint32_t Vl[16 * AVSTR];
    __shared__ uint32_t Ph[8][16 * PSTR];
    __shared__ uint32_t Pl[8][16 * PSTR];
    __shared__ float    Bs[32];

    const int tid  = threadIdx.x;
    const int lane = tid & 31, wid = tid >> 5;
    const int gid  = lane >> 2, tig = lane & 3;
    const int b = blockIdx.z, h = blockIdx.y;
    const int t0 = blockIdx.x * 128;

    const size_t kvBase = ((size_t)b * T_) * D_ + h * DK_;

    // Q fragments: tf32-rounded registers
    uint32_t Qr[8][4];
    {
        const int r0 = t0 + wid * 16 + gid;
        const float* q0 = Qg + ((size_t)(b * T_) + r0) * D_ + h * DK_;
        const float* q1 = q0 + 8 * D_;
#pragma unroll
        for (int ks = 0; ks < 8; ks++) {
            int c = ks * 8 + tig;
            Qr[ks][0] = f2tf32(q0[c]);
            Qr[ks][1] = f2tf32(q1[c]);
            Qr[ks][2] = f2tf32(q0[c + 4]);
            Qr[ks][3] = f2tf32(q1[c + 4]);
        }
    }

    float oacc[8][4];
#pragma unroll
    for (int nt = 0; nt < 8; nt++)
#pragma unroll
        for (int i = 0; i < 4; i++) oacc[nt][i] = 0.f;
    float m0 = -1e30f, m1 = -1e30f, l0 = 0.f, l1 = 0.f;

    // fill mappings + prefetch
    const int frow = tid >> 4;
    const int fc4  = (tid & 15) * 4;
    const float* kRow = Kg + kvBase + (size_t)frow * D_ + fc4;

    const int vp  = tid >> 4;
    const int vcg = (tid & 15) * 4;
    const float* vRow0 = Vg + kvBase + (size_t)(2 * vp) * D_ + vcg;
    const float* vRow1 = vRow0 + D_;

    float4 ka  = *(const float4*)(kRow);
    float4 kb4 = *(const float4*)(kRow + 16 * D_);
    float4 va0 = *(const float4*)(vRow0);
    float4 va1 = *(const float4*)(vRow1);

    for (int s0 = 0; s0 < T_; s0 += 32) {
        __syncthreads();
        {
            float* kd0 = &Ks[frow * KPAD + fc4];
            kd0[0] = __uint_as_float(f2tf32(ka.x));
            kd0[1] = __uint_as_float(f2tf32(ka.y));
            kd0[2] = __uint_as_float(f2tf32(ka.z));
            kd0[3] = __uint_as_float(f2tf32(ka.w));
            float* kd1 = &Ks[(frow + 16) * KPAD + fc4];
            kd1[0] = __uint_as_float(f2tf32(kb4.x));
            kd1[1] = __uint_as_float(f2tf32(kb4.y));
            kd1[2] = __uint_as_float(f2tf32(kb4.z));
            kd1[3] = __uint_as_float(f2tf32(kb4.w));

            float h0, lo0, h1, lo1;
            uint32_t* vhp = &Vh[vp * AVSTR + vcg];
            uint32_t* vlp = &Vl[vp * AVSTR + vcg];
            split_bf(va0.x, h0, lo0); split_bf(va1.x, h1, lo1);
            vhp[0] = packbf(h0, h1);  vlp[0] = packbf(lo0, lo1);
            split_bf(va0.y, h0, lo0); split_bf(va1.y, h1, lo1);
            vhp[1] = packbf(h0, h1);  vlp[1] = packbf(lo0, lo1);
            split_bf(va0.z, h0, lo0); split_bf(va1.z, h1, lo1);
            vhp[2] = packbf(h0, h1);  vlp[2] = packbf(lo0, lo1);
            split_bf(va0.w, h0, lo0); split_bf(va1.w, h1, lo1);
            vhp[3] = packbf(h0, h1);  vlp[3] = packbf(lo0, lo1);

            if (tid < 32) Bs[tid] = g_bias[b * T_ + s0 + tid];
        }
        __syncthreads();

        if (s0 + 32 < T_) {
            ka  = *(const float4*)(kRow + (size_t)(s0 + 32) * D_);
            kb4 = *(const float4*)(kRow + (size_t)(s0 + 48) * D_);
            va0 = *(const float4*)(vRow0 + (size_t)(s0 + 32) * D_);
            va1 = *(const float4*)(vRow1 + (size_t)(s0 + 32) * D_);
        }

        // ---- S = Q K^T (tf32 x1) ----
        float sacc[4][4];
#pragma unroll
        for (int nt = 0; nt < 4; nt++)
#pragma unroll
            for (int i = 0; i < 4; i++) sacc[nt][i] = 0.f;
#pragma unroll
        for (int ks = 0; ks < 8; ks++) {
            const int kb = ks * 8;
#pragma unroll
            for (int nt = 0; nt < 4; nt++) {
                const float* kp = &Ks[(nt * 8 + gid) * KPAD + kb + tig];
                uint32_t bf[2];
                bf[0] = __float_as_uint(kp[0]);
                bf[1] = __float_as_uint(kp[4]);
                mma_tf32(sacc[nt], Qr[ks], bf);
            }
        }

        // ---- scale + bias, online softmax ----
        float sv[4][4];
#pragma unroll
        for (int nt = 0; nt < 4; nt++) {
            int c0 = nt * 8 + 2 * tig;
            float bb0 = Bs[c0], bb1 = Bs[c0 + 1];
            sv[nt][0] = sacc[nt][0] * SCALE_ + bb0;
            sv[nt][1] = sacc[nt][1] * SCALE_ + bb1;
            sv[nt][2] = sacc[nt][2] * SCALE_ + bb0;
            sv[nt][3] = sacc[nt][3] * SCALE_ + bb1;
        }
        float mx0 = fmaxf(fmaxf(sv[0][0], sv[0][1]), fmaxf(sv[1][0], sv[1][1]));
        mx0 = fmaxf(mx0, fmaxf(fmaxf(sv[2][0], sv[2][1]), fmaxf(sv[3][0], sv[3][1])));
        float mx1 = fmaxf(fmaxf(sv[0][2], sv[0][3]), fmaxf(sv[1][2], sv[1][3]));
        mx1 = fmaxf(mx1, fmaxf(fmaxf(sv[2][2], sv[2][3]), fmaxf(sv[3][2], sv[3][3])));
        mx0 = fmaxf(mx0, __shfl_xor_sync(0xffffffffu, mx0, 1));
        mx0 = fmaxf(mx0, __shfl_xor_sync(0xffffffffu, mx0, 2));
        mx1 = fmaxf(mx1, __shfl_xor_sync(0xffffffffu, mx1, 1));
        mx1 = fmaxf(mx1, __shfl_xor_sync(0xffffffffu, mx1, 2));

        float m0n = fmaxf(m0, mx0), m1n = fmaxf(m1, mx1);
        float c0f = __expf(m0 - m0n), c1f = __expf(m1 - m1n);
        m0 = m0n; m1 = m1n;

        float rs0 = 0.f, rs1 = 0.f;
#pragma unroll
        for (int nt = 0; nt < 4; nt++) {
            float p0 = __expf(sv[nt][0] - m0n);
            float p1 = __expf(sv[nt][1] - m0n);
            float p2 = __expf(sv[nt][2] - m1n);
            float p3 = __expf(sv[nt][3] - m1n);
            rs0 += p0 + p1; rs1 += p2 + p3;
            float h0, lo0, h1, lo1;
            int pi = nt * 4 + tig;
            split_bf(p0, h0, lo0); split_bf(p1, h1, lo1);
            Ph[wid][gid * PSTR + pi] = packbf(h0, h1);
            Pl[wid][gid * PSTR + pi] = packbf(lo0, lo1);
            split_bf(p2, h0, lo0); split_bf(p3, h1, lo1);
            Ph[wid][(gid + 8) * PSTR + pi] = packbf(h0, h1);
            Pl[wid][(gid + 8) * PSTR + pi] = packbf(lo0, lo1);
        }
        rs0 += __shfl_xor_sync(0xffffffffu, rs0, 1);
        rs0 += __shfl_xor_sync(0xffffffffu, rs0, 2);
        rs1 += __shfl_xor_sync(0xffffffffu, rs1, 1);
        rs1 += __shfl_xor_sync(0xffffffffu, rs1, 2);
        l0 = l0 * c0f + rs0;
        l1 = l1 * c1f + rs1;
#pragma unroll
        for (int nt = 0; nt < 8; nt++) {
            oacc[nt][0] *= c0f; oacc[nt][1] *= c0f;
            oacc[nt][2] *= c1f; oacc[nt][3] *= c1f;
        }
        __syncwarp();

        // ---- O += P V (bf16 x3, m16n8k16) ----
#pragma unroll
        for (int kk = 0; kk < 2; kk++) {
            uint32_t ah[4], al[4];
            ah[0] = Ph[wid][gid * PSTR + kk * 8 + tig];
            ah[1] = Ph[wid][(gid + 8) * PSTR + kk * 8 + tig];
            ah[2] = Ph[wid][gid * PSTR + kk * 8 + tig + 4];
            ah[3] = Ph[wid][(gid + 8) * PSTR + kk * 8 + tig + 4];
            al[0] = Pl[wid][gid * PSTR + kk * 8 + tig];
            al[1] = Pl[wid][(gid + 8) * PSTR + kk * 8 + tig];
            al[2] = Pl[wid][gid * PSTR + kk * 8 + tig + 4];
            al[3] = Pl[wid][(gid + 8) * PSTR + kk * 8 + tig + 4];
#pragma unroll
            for (int nt = 0; nt < 8; nt++) {
                uint32_t bh[2], bl[2];
                bh[0] = Vh[(kk * 8 + tig) * AVSTR + nt * 8 + gid];
                bh[1] = Vh[(kk * 8 + tig + 4) * AVSTR + nt * 8 + gid];
                bl[0] = Vl[(kk * 8 + tig) * AVSTR + nt * 8 + gid];
                bl[1] = Vl[(kk * 8 + tig + 4) * AVSTR + nt * 8 + gid];
                mma_bf16(oacc[nt], ah, bh);
                mma_bf16(oacc[nt], al, bh);
                mma_bf16(oacc[nt], ah, bl);
            }
        }
        __syncwarp();
    }

    // ---- epilogue ----
    float inv0 = 1.f / l0, inv1 = 1.f / l1;
    const int gr0 = t0 + wid * 16 + gid;
    float* o0 = CTX + ((size_t)(b * T_) + gr0) * D_ + h * DK_;
    float* o1 = o0 + 8 * D_;
#pragma unroll
    for (int nt = 0; nt < 8; nt++) {
        int c = nt * 8 + 2 * tig;
        *(float2*)(o0 + c) = make_float2(oacc[nt][0] * inv0, oacc[nt][1] * inv0);
        *(float2*)(o1 + c) = make_float2(oacc[nt][2] * inv1, oacc[nt][3] * inv1);
    }
}

// ---------------- launch ----------------
extern "C" void kernel_launch(void* const* d_in, const int* in_sizes, int n_in,
                              void* d_out, int out_size)
{
    const float* query = (const float*)d_in[0];
    const float* key   = (const float*)d_in[1];
    const float* value = (const float*)d_in[2];
    const void*  mask  = d_in[3];
    const float* Wq = (const float*)d_in[4];  const float* bq = (const float*)d_in[5];
    const float* Wk = (const float*)d_in[6];  const float* bk = (const float*)d_in[7];
    const float* Wv = (const float*)d_in[8];  const float* bv = (const float*)d_in[9];
    const float* Wo = (const float*)d_in[10]; const float* bo = (const float*)d_in[11];

    float *Qb, *Kb, *Vb, *Cb;
    cudaGetSymbolAddress((void**)&Qb, g_Q);
    cudaGetSymbolAddress((void**)&Kb, g_K);
    cudaGetSymbolAddress((void**)&Vb, g_V);
    cudaGetSymbolAddress((void**)&Cb, g_CTX);

    detect_mask_kernel<<<1, 256>>>((const unsigned int*)mask);
    build_bias_kernel<<<(M_ + 255) / 256, 256>>>(mask);

    dim3 gg(D_ / 128, M_ / 128);   // (8, 32) = 256 blocks
    gemm_bf16x3_kernel<<<gg, 256>>>(query, Wq, bq, Qb);
    gemm_bf16x3_kernel<<<gg, 256>>>(key,   Wk, bk, Kb);
    gemm_bf16x3_kernel<<<gg, 256>>>(value, Wv, bv, Vb);

    attn_mma_kernel<<<dim3(T_ / 128, H_, B_), 256>>>(Qb, Kb, Vb, Cb);

    gemm_bf16x3_kernel<<<gg, 256>>>(Cb, Wo, bo, (float*)d_out);
}

// round 12
// speedup vs baseline: 1.4110x; 1.2131x over previous
#include <cuda_runtime.h>
#include <cuda_fp16.h>
#include <cstdint>

#define B_ 2
#define T_ 2048
#define D_ 1024
#define H_ 16
#define DK_ 64
#define M_ (B_*T_)
#define SCALE_ 0.125f

// ---------------- scratch ----------------
__device__ float g_Q[M_*D_];
__device__ float g_K[M_*D_];
__device__ float g_V[M_*D_];
__device__ float g_CTX[M_*D_];
__device__ float g_bias[M_];
__device__ int   g_maskmode;

// ---------------- mask dtype detection ----------------
__global__ void detect_mask_kernel(const unsigned int* __restrict__ w) {
    __shared__ int s_badint, s_badfloat;
    if (threadIdx.x == 0) { s_badint = 0; s_badfloat = 0; }
    __syncthreads();
    int bi = 0, bf = 0;
    for (int i = threadIdx.x; i < 1024; i += blockDim.x) {
        unsigned v = w[i];
        if (v > 1u) bi = 1;
        if (v != 0u && v != 0x3F800000u) bf = 1;
    }
    if (bi) atomicOr(&s_badint, 1);
    if (bf) atomicOr(&s_badfloat, 1);
    __syncthreads();
    if (threadIdx.x == 0)
        g_maskmode = (!s_badint) ? 0 : ((!s_badfloat) ? 1 : 2);
}

__global__ void build_bias_kernel(const void* __restrict__ mask) {
    int i = blockIdx.x * blockDim.x + threadIdx.x;
    if (i >= M_) return;
    int mode = g_maskmode;
    bool keep;
    if (mode == 0)      keep = ((const int*)mask)[i] != 0;
    else if (mode == 1) keep = ((const float*)mask)[i] != 0.0f;
    else                keep = ((const unsigned char*)mask)[i] != 0;
    g_bias[i] = keep ? 0.0f : -1e30f;
}

// ---------------- mma / ldmatrix helpers ----------------
__device__ __forceinline__ void mma_tf32(float* d, const uint32_t* a, const uint32_t* b) {
    asm volatile(
        "mma.sync.aligned.m16n8k8.row.col.f32.tf32.tf32.f32 "
        "{%0,%1,%2,%3}, {%4,%5,%6,%7}, {%8,%9}, {%0,%1,%2,%3};"
        : "+f"(d[0]), "+f"(d[1]), "+f"(d[2]), "+f"(d[3])
        : "r"(a[0]), "r"(a[1]), "r"(a[2]), "r"(a[3]), "r"(b[0]), "r"(b[1]));
}

__device__ __forceinline__ void mma_f16(float* d, const uint32_t* a, const uint32_t* b) {
    asm volatile(
        "mma.sync.aligned.m16n8k16.row.col.f32.f16.f16.f32 "
        "{%0,%1,%2,%3}, {%4,%5,%6,%7}, {%8,%9}, {%0,%1,%2,%3};"
        : "+f"(d[0]), "+f"(d[1]), "+f"(d[2]), "+f"(d[3])
        : "r"(a[0]), "r"(a[1]), "r"(a[2]), "r"(a[3]), "r"(b[0]), "r"(b[1]));
}

__device__ __forceinline__ void ldsm4(uint32_t& r0, uint32_t& r1, uint32_t& r2, uint32_t& r3,
                                      uint32_t saddr) {
    asm volatile("ldmatrix.sync.aligned.m8n8.x4.shared.b16 {%0,%1,%2,%3}, [%4];"
                 : "=r"(r0), "=r"(r1), "=r"(r2), "=r"(r3) : "r"(saddr));
}

__device__ __forceinline__ uint32_t f2tf32(float x) {
    uint32_t r;
    asm("cvt.rna.tf32.f32 %0, %1;" : "=r"(r) : "f"(x));
    return r;
}

__device__ __forceinline__ void split_h(float x, float& h, float& l) {
    h = __half2float(__float2half_rn(x));
    l = x - h;
}

__device__ __forceinline__ uint32_t packh(float a, float b) {
    __half2 t = __floats2half2_rn(a, b);   // low half = a (even k)
    return *reinterpret_cast<uint32_t*>(&t);
}

__device__ __forceinline__ uint32_t smem_u32(const void* p) {
    return (uint32_t)__cvta_generic_to_shared(p);
}

// ================= fp16 x2 GEMM, 128x128 tile, ldmatrix frags ==================
// C = A @ W^T + b, with A split hi/lo fp16 (2 planes) and W rounded fp16 (1 plane):
// acc = Ah*Wh + Al*Wh = (exact A) * fp16(W).  8 warps (2m x 4n), k-step 16.
#define GST 12

struct GemmBatch {
    const float* A[3];
    const float* W[3];
    const float* bias[3];
    float*       C[3];
};

__global__ __launch_bounds__(256, 2) void gemm_f16x2_kernel(GemmBatch gb)
{
    __shared__ __align__(16) uint32_t Ahs[2][128 * GST];
    __shared__ __align__(16) uint32_t Als[2][128 * GST];
    __shared__ __align__(16) uint32_t Bhs[2][128 * GST];

    const int bz = blockIdx.z;
    const float* __restrict__ A    = gb.A[bz];
    const float* __restrict__ W    = gb.W[bz];
    const float* __restrict__ bvec = gb.bias[bz];
    float* __restrict__ C          = gb.C[bz];

    const int tid  = threadIdx.x;
    const int lane = tid & 31, wid = tid >> 5;
    const int wm   = (wid >> 2) * 64;
    const int wn   = (wid & 3) * 32;
    const int gid  = lane >> 2, tig = lane & 3;
    const int m0 = blockIdx.y * 128;
    const int n0 = blockIdx.x * 128;

    float acc[4][4][4];
#pragma unroll
    for (int mt = 0; mt < 4; mt++)
#pragma unroll
        for (int nt = 0; nt < 4; nt++)
#pragma unroll
            for (int i = 0; i < 4; i++) acc[mt][nt][i] = 0.f;

    const int frow = tid >> 1;
    const int kh   = tid & 1;
    const float* Ag = A + (size_t)(m0 + frow) * 1024 + kh * 8;
    const float* Wg = W + (size_t)(n0 + frow) * 1024 + kh * 8;

    const uint32_t aOff = ((lane & 15) * GST + (lane >> 4) * 4) * 4;
    const uint32_t bOff = ((((lane >> 4) * 8) + (lane & 7)) * GST + ((lane >> 3) & 1) * 4) * 4;

    const uint32_t sAh = smem_u32(Ahs), sAl = smem_u32(Als);
    const uint32_t sBh = smem_u32(Bhs);
    const uint32_t PBUF = 128 * GST * 4;

    float4 pa0, pa1, pw0, pw1;
    pa0 = *(const float4*)(Ag);
    pa1 = *(const float4*)(Ag + 4);
    pw0 = *(const float4*)(Wg);
    pw1 = *(const float4*)(Wg + 4);

#define GSTORE(BUF)                                                            \
    do {                                                                       \
        float h0,h1,h2,h3,h4,h5,h6,h7,l0,l1,l2,l3,l4,l5,l6,l7;                 \
        split_h(pa0.x,h0,l0); split_h(pa0.y,h1,l1);                            \
        split_h(pa0.z,h2,l2); split_h(pa0.w,h3,l3);                            \
        split_h(pa1.x,h4,l4); split_h(pa1.y,h5,l5);                            \
        split_h(pa1.z,h6,l6); split_h(pa1.w,h7,l7);                            \
        *(uint4*)&Ahs[BUF][frow*GST + kh*4] =                                  \
            make_uint4(packh(h0,h1),packh(h2,h3),packh(h4,h5),packh(h6,h7));   \
        *(uint4*)&Als[BUF][frow*GST + kh*4] =                                  \
            make_uint4(packh(l0,l1),packh(l2,l3),packh(l4,l5),packh(l6,l7));   \
        *(uint4*)&Bhs[BUF][frow*GST + kh*4] =                                  \
            make_uint4(packh(pw0.x,pw0.y),packh(pw0.z,pw0.w),                  \
                       packh(pw1.x,pw1.y),packh(pw1.z,pw1.w));                 \
    } while (0)

#define GCOMP(BUF)                                                            \
    do {                                                                      \
        uint32_t a_h[4][4], a_l[4][4], b_h[4][2];                             \
        _Pragma("unroll")                                                     \
        for (int mt = 0; mt < 4; mt++) {                                      \
            uint32_t ro = (uint32_t)((wm + mt * 16) * GST * 4);               \
            ldsm4(a_h[mt][0], a_h[mt][1], a_h[mt][2], a_h[mt][3],             \
                  sAh + (BUF) * PBUF + ro + aOff);                            \
            ldsm4(a_l[mt][0], a_l[mt][1], a_l[mt][2], a_l[mt][3],             \
                  sAl + (BUF) * PBUF + ro + aOff);                            \
        }                                                                     \
        _Pragma("unroll")                                                     \
        for (int ntp = 0; ntp < 2; ntp++) {                                   \
            uint32_t ro = (uint32_t)((wn + ntp * 16) * GST * 4);              \
            ldsm4(b_h[2*ntp][0], b_h[2*ntp][1], b_h[2*ntp+1][0], b_h[2*ntp+1][1], \
                  sBh + (BUF) * PBUF + ro + bOff);                            \
        }                                                                     \
        _Pragma("unroll")                                                     \
        for (int mt = 0; mt < 4; mt++)                                        \
            _Pragma("unroll")                                                 \
            for (int nt = 0; nt < 4; nt++) {                                  \
                mma_f16(acc[mt][nt], a_h[mt], b_h[nt]);                       \
                mma_f16(acc[mt][nt], a_l[mt], b_h[nt]);                       \
            }                                                                 \
    } while (0)

    GSTORE(0);
    __syncthreads();

    int buf = 0;
    for (int k0 = 16; k0 < 1024; k0 += 16) {
        pa0 = *(const float4*)(Ag + k0);
        pa1 = *(const float4*)(Ag + k0 + 4);
        pw0 = *(const float4*)(Wg + k0);
        pw1 = *(const float4*)(Wg + k0 + 4);
        if (buf == 0) GCOMP(0); else GCOMP(1);
        __syncthreads();
        if (buf == 0) GSTORE(1); else GSTORE(0);
        __syncthreads();
        buf ^= 1;
    }
    if (buf == 0) GCOMP(0); else GCOMP(1);

#pragma unroll
    for (int mt = 0; mt < 4; mt++) {
#pragma unroll
        for (int nt = 0; nt < 4; nt++) {
            int gm = m0 + wm + mt * 16 + gid;
            int gn = n0 + wn + nt * 8 + tig * 2;
            float b0 = __ldg(bvec + gn);
            float b1 = __ldg(bvec + gn + 1);
            *(float2*)&C[(size_t)gm * 1024 + gn] =
                make_float2(acc[mt][nt][0] + b0, acc[mt][nt][1] + b1);
            *(float2*)&C[(size_t)(gm + 8) * 1024 + gn] =
                make_float2(acc[mt][nt][2] + b0, acc[mt][nt][3] + b1);
        }
    }
}

// ================= tensor-core flash attention ==================
// QK^T: tf32 x1. P*V: fp16 x2 — P split hi/lo (2 planes), V rounded fp16 (1 plane).
#define KPAD 68
#define AVSTR 72
#define PSTR 20

__global__ __launch_bounds__(256) void attn_mma_kernel(
    const float* __restrict__ Qg, const float* __restrict__ Kg,
    const float* __restrict__ Vg, float* __restrict__ CTX)
{
    __shared__ float    Ks[32 * KPAD];
    __shared__ uint32_t Vh[16 * AVSTR];
    __shared__ uint32_t Ph[8][16 * PSTR];
    __shared__ uint32_t Pl[8][16 * PSTR];
    __shared__ float    Bs[32];

    const int tid  = threadIdx.x;
    const int lane = tid & 31, wid = tid >> 5;
    const int gid  = lane >> 2, tig = lane & 3;
    const int b = blockIdx.z, h = blockIdx.y;
    const int t0 = blockIdx.x * 128;

    const size_t kvBase = ((size_t)b * T_) * D_ + h * DK_;

    uint32_t Qr[8][4];
    {
        const int r0 = t0 + wid * 16 + gid;
        const float* q0 = Qg + ((size_t)(b * T_) + r0) * D_ + h * DK_;
        const float* q1 = q0 + 8 * D_;
#pragma unroll
        for (int ks = 0; ks < 8; ks++) {
            int c = ks * 8 + tig;
            Qr[ks][0] = f2tf32(q0[c]);
            Qr[ks][1] = f2tf32(q1[c]);
            Qr[ks][2] = f2tf32(q0[c + 4]);
            Qr[ks][3] = f2tf32(q1[c + 4]);
        }
    }

    float oacc[8][4];
#pragma unroll
    for (int nt = 0; nt < 8; nt++)
#pragma unroll
        for (int i = 0; i < 4; i++) oacc[nt][i] = 0.f;
    float m0 = -1e30f, m1 = -1e30f, l0 = 0.f, l1 = 0.f;

    const int frow = tid >> 4;
    const int fc4  = (tid & 15) * 4;
    const float* kRow = Kg + kvBase + (size_t)frow * D_ + fc4;

    const int vp  = tid >> 4;
    const int vcg = (tid & 15) * 4;
    const float* vRow0 = Vg + kvBase + (size_t)(2 * vp) * D_ + vcg;
    const float* vRow1 = vRow0 + D_;

    float4 ka  = *(const float4*)(kRow);
    float4 kb4 = *(const float4*)(kRow + 16 * D_);
    float4 va0 = *(const float4*)(vRow0);
    float4 va1 = *(const float4*)(vRow1);

    for (int s0 = 0; s0 < T_; s0 += 32) {
        __syncthreads();
        {
            float* kd0 = &Ks[frow * KPAD + fc4];
            kd0[0] = __uint_as_float(f2tf32(ka.x));
            kd0[1] = __uint_as_float(f2tf32(ka.y));
            kd0[2] = __uint_as_float(f2tf32(ka.z));
            kd0[3] = __uint_as_float(f2tf32(ka.w));
            float* kd1 = &Ks[(frow + 16) * KPAD + fc4];
            kd1[0] = __uint_as_float(f2tf32(kb4.x));
            kd1[1] = __uint_as_float(f2tf32(kb4.y));
            kd1[2] = __uint_as_float(f2tf32(kb4.z));
            kd1[3] = __uint_as_float(f2tf32(kb4.w));

            uint32_t* vhp = &Vh[vp * AVSTR + vcg];
            vhp[0] = packh(va0.x, va1.x);
            vhp[1] = packh(va0.y, va1.y);
            vhp[2] = packh(va0.z, va1.z);
            vhp[3] = packh(va0.w, va1.w);

            if (tid < 32) Bs[tid] = g_bias[b * T_ + s0 + tid];
        }
        __syncthreads();

        if (s0 + 32 < T_) {
            ka  = *(const float4*)(kRow + (size_t)(s0 + 32) * D_);
            kb4 = *(const float4*)(kRow + (size_t)(s0 + 48) * D_);
            va0 = *(const float4*)(vRow0 + (size_t)(s0 + 32) * D_);
            va1 = *(const float4*)(vRow1 + (size_t)(s0 + 32) * D_);
        }

        // ---- S = Q K^T (tf32 x1) ----
        float sacc[4][4];
#pragma unroll
        for (int nt = 0; nt < 4; nt++)
#pragma unroll
            for (int i = 0; i < 4; i++) sacc[nt][i] = 0.f;
#pragma unroll
        for (int ks = 0; ks < 8; ks++) {
            const int kb = ks * 8;
#pragma unroll
            for (int nt = 0; nt < 4; nt++) {
                const float* kp = &Ks[(nt * 8 + gid) * KPAD + kb + tig];
                uint32_t bf[2];
                bf[0] = __float_as_uint(kp[0]);
                bf[1] = __float_as_uint(kp[4]);
                mma_tf32(sacc[nt], Qr[ks], bf);
            }
        }

        // ---- scale + bias, online softmax ----
        float sv[4][4];
#pragma unroll
        for (int nt = 0; nt < 4; nt++) {
            int c0 = nt * 8 + 2 * tig;
            float bb0 = Bs[c0], bb1 = Bs[c0 + 1];
            sv[nt][0] = sacc[nt][0] * SCALE_ + bb0;
            sv[nt][1] = sacc[nt][1] * SCALE_ + bb1;
            sv[nt][2] = sacc[nt][2] * SCALE_ + bb0;
            sv[nt][3] = sacc[nt][3] * SCALE_ + bb1;
        }
        float mx0 = fmaxf(fmaxf(sv[0][0], sv[0][1]), fmaxf(sv[1][0], sv[1][1]));
        mx0 = fmaxf(mx0, fmaxf(fmaxf(sv[2][0], sv[2][1]), fmaxf(sv[3][0], sv[3][1])));
        float mx1 = fmaxf(fmaxf(sv[0][2], sv[0][3]), fmaxf(sv[1][2], sv[1][3]));
        mx1 = fmaxf(mx1, fmaxf(fmaxf(sv[2][2], sv[2][3]), fmaxf(sv[3][2], sv[3][3])));
        mx0 = fmaxf(mx0, __shfl_xor_sync(0xffffffffu, mx0, 1));
        mx0 = fmaxf(mx0, __shfl_xor_sync(0xffffffffu, mx0, 2));
        mx1 = fmaxf(mx1, __shfl_xor_sync(0xffffffffu, mx1, 1));
        mx1 = fmaxf(mx1, __shfl_xor_sync(0xffffffffu, mx1, 2));

        float m0n = fmaxf(m0, mx0), m1n = fmaxf(m1, mx1);
        float c0f = __expf(m0 - m0n), c1f = __expf(m1 - m1n);
        m0 = m0n; m1 = m1n;

        float rs0 = 0.f, rs1 = 0.f;
#pragma unroll
        for (int nt = 0; nt < 4; nt++) {
            float p0 = __expf(sv[nt][0] - m0n);
            float p1 = __expf(sv[nt][1] - m0n);
            float p2 = __expf(sv[nt][2] - m1n);
            float p3 = __expf(sv[nt][3] - m1n);
            rs0 += p0 + p1; rs1 += p2 + p3;
            float h0, lo0, h1, lo1;
            int pi = nt * 4 + tig;
            split_h(p0, h0, lo0); split_h(p1, h1, lo1);
            Ph[wid][gid * PSTR + pi] = packh(h0, h1);
            Pl[wid][gid * PSTR + pi] = packh(lo0, lo1);
            split_h(p2, h0, lo0); split_h(p3, h1, lo1);
            Ph[wid][(gid + 8) * PSTR + pi] = packh(h0, h1);
            Pl[wid][(gid + 8) * PSTR + pi] = packh(lo0, lo1);
        }
        rs0 += __shfl_xor_sync(0xffffffffu, rs0, 1);
        rs0 += __shfl_xor_sync(0xffffffffu, rs0, 2);
        rs1 += __shfl_xor_sync(0xffffffffu, rs1, 1);
        rs1 += __shfl_xor_sync(0xffffffffu, rs1, 2);
        l0 = l0 * c0f + rs0;
        l1 = l1 * c1f + rs1;
#pragma unroll
        for (int nt = 0; nt < 8; nt++) {
            oacc[nt][0] *= c0f; oacc[nt][1] *= c0f;
            oacc[nt][2] *= c1f; oacc[nt][3] *= c1f;
        }
        __syncwarp();

        // ---- O += P V (fp16 x2: (Ph+Pl) * fp16(V)) ----
#pragma unroll
        for (int kk = 0; kk < 2; kk++) {
            uint32_t ah[4], al[4];
            ah[0] = Ph[wid][gid * PSTR + kk * 8 + tig];
            ah[1] = Ph[wid][(gid + 8) * PSTR + kk * 8 + tig];
            ah[2] = Ph[wid][gid * PSTR + kk * 8 + tig + 4];
            ah[3] = Ph[wid][(gid + 8) * PSTR + kk * 8 + tig + 4];
            al[0] = Pl[wid][gid * PSTR + kk * 8 + tig];
            al[1] = Pl[wid][(gid + 8) * PSTR + kk * 8 + tig];
            al[2] = Pl[wid][gid * PSTR + kk * 8 + tig + 4];
            al[3] = Pl[wid][(gid + 8) * PSTR + kk * 8 + tig + 4];
#pragma unroll
            for (int nt = 0; nt < 8; nt++) {
                uint32_t bh[2];
                bh[0] = Vh[(kk * 8 + tig) * AVSTR + nt * 8 + gid];
                bh[1] = Vh[(kk * 8 + tig + 4) * AVSTR + nt * 8 + gid];
                mma_f16(oacc[nt], ah, bh);
                mma_f16(oacc[nt], al, bh);
            }
        }
        __syncwarp();
    }

    float inv0 = 1.f / l0, inv1 = 1.f / l1;
    const int gr0 = t0 + wid * 16 + gid;
    float* o0 = CTX + ((size_t)(b * T_) + gr0) * D_ + h * DK_;
    float* o1 = o0 + 8 * D_;
#pragma unroll
    for (int nt = 0; nt < 8; nt++) {
        int c = nt * 8 + 2 * tig;
        *(float2*)(o0 + c) = make_float2(oacc[nt][0] * inv0, oacc[nt][1] * inv0);
        *(float2*)(o1 + c) = make_float2(oacc[nt][2] * inv1, oacc[nt][3] * inv1);
    }
}

// ---------------- launch ----------------
extern "C" void kernel_launch(void* const* d_in, const int* in_sizes, int n_in,
                              void* d_out, int out_size)
{
    const float* query = (const float*)d_in[0];
    const float* key   = (const float*)d_in[1];
    const float* value = (const float*)d_in[2];
    const void*  mask  = d_in[3];
    const float* Wq = (const float*)d_in[4];  const float* bq = (const float*)d_in[5];
    const float* Wk = (const float*)d_in[6];  const float* bk = (const float*)d_in[7];
    const float* Wv = (const float*)d_in[8];  const float* bv = (const float*)d_in[9];
    const float* Wo = (const float*)d_in[10]; const float* bo = (const float*)d_in[11];

    float *Qb, *Kb, *Vb, *Cb;
    cudaGetSymbolAddress((void**)&Qb, g_Q);
    cudaGetSymbolAddress((void**)&Kb, g_K);
    cudaGetSymbolAddress((void**)&Vb, g_V);
    cudaGetSymbolAddress((void**)&Cb, g_CTX);

    detect_mask_kernel<<<1, 256>>>((const unsigned int*)mask);
    build_bias_kernel<<<(M_ + 255) / 256, 256>>>(mask);

    // batched QKV projections in one launch
    GemmBatch gqkv;
    gqkv.A[0] = query; gqkv.A[1] = key; gqkv.A[2] = value;
    gqkv.W[0] = Wq;    gqkv.W[1] = Wk;  gqkv.W[2] = Wv;
    gqkv.bias[0] = bq; gqkv.bias[1] = bk; gqkv.bias[2] = bv;
    gqkv.C[0] = Qb;    gqkv.C[1] = Kb;  gqkv.C[2] = Vb;
    gemm_f16x2_kernel<<<dim3(D_ / 128, M_ / 128, 3), 256>>>(gqkv);

    attn_mma_kernel<<<dim3(T_ / 128, H_, B_), 256>>>(Qb, Kb, Vb, Cb);

    GemmBatch go;
    go.A[0] = Cb; go.A[1] = Cb; go.A[2] = Cb;
    go.W[0] = Wo; go.W[1] = Wo; go.W[2] = Wo;
    go.bias[0] = bo; go.bias[1] = bo; go.bias[2] = bo;
    go.C[0] = (float*)d_out; go.C[1] = (float*)d_out; go.C[2] = (float*)d_out;
    gemm_f16x2_kernel<<<dim3(D_ / 128, M_ / 128, 1), 256>>>(go);
}

// round 13
// speedup vs baseline: 1.5606x; 1.1060x over previous
#include <cuda_runtime.h>
#include <cuda_fp16.h>
#include <cstdint>

#define B_ 2
#define T_ 2048
#define D_ 1024
#define H_ 16
#define DK_ 64
#define M_ (B_*T_)
#define SCALE_ 0.125f

// ---------------- scratch ----------------
__device__ float g_Q[M_*D_];
__device__ float g_K[M_*D_];
__device__ float g_V[M_*D_];
__device__ float g_CTX[M_*D_];
__device__ float g_bias[M_];
__device__ int   g_maskmode;

// ---------------- mask dtype detection ----------------
__global__ void detect_mask_kernel(const unsigned int* __restrict__ w) {
    __shared__ int s_badint, s_badfloat;
    if (threadIdx.x == 0) { s_badint = 0; s_badfloat = 0; }
    __syncthreads();
    int bi = 0, bf = 0;
    for (int i = threadIdx.x; i < 1024; i += blockDim.x) {
        unsigned v = w[i];
        if (v > 1u) bi = 1;
        if (v != 0u && v != 0x3F800000u) bf = 1;
    }
    if (bi) atomicOr(&s_badint, 1);
    if (bf) atomicOr(&s_badfloat, 1);
    __syncthreads();
    if (threadIdx.x == 0)
        g_maskmode = (!s_badint) ? 0 : ((!s_badfloat) ? 1 : 2);
}

__global__ void build_bias_kernel(const void* __restrict__ mask) {
    int i = blockIdx.x * blockDim.x + threadIdx.x;
    if (i >= M_) return;
    int mode = g_maskmode;
    bool keep;
    if (mode == 0)      keep = ((const int*)mask)[i] != 0;
    else if (mode == 1) keep = ((const float*)mask)[i] != 0.0f;
    else                keep = ((const unsigned char*)mask)[i] != 0;
    g_bias[i] = keep ? 0.0f : -1e30f;
}

// ---------------- mma / ldmatrix helpers ----------------
__device__ __forceinline__ void mma_f16(float* d, const uint32_t* a, const uint32_t* b) {
    asm volatile(
        "mma.sync.aligned.m16n8k16.row.col.f32.f16.f16.f32 "
        "{%0,%1,%2,%3}, {%4,%5,%6,%7}, {%8,%9}, {%0,%1,%2,%3};"
        : "+f"(d[0]), "+f"(d[1]), "+f"(d[2]), "+f"(d[3])
        : "r"(a[0]), "r"(a[1]), "r"(a[2]), "r"(a[3]), "r"(b[0]), "r"(b[1]));
}

__device__ __forceinline__ void ldsm4(uint32_t& r0, uint32_t& r1, uint32_t& r2, uint32_t& r3,
                                      uint32_t saddr) {
    asm volatile("ldmatrix.sync.aligned.m8n8.x4.shared.b16 {%0,%1,%2,%3}, [%4];"
                 : "=r"(r0), "=r"(r1), "=r"(r2), "=r"(r3) : "r"(saddr));
}

__device__ __forceinline__ void split_h(float x, float& h, float& l) {
    h = __half2float(__float2half_rn(x));
    l = x - h;
}

__device__ __forceinline__ uint32_t packh(float a, float b) {
    __half2 t = __floats2half2_rn(a, b);   // low half = a (even k)
    return *reinterpret_cast<uint32_t*>(&t);
}

__device__ __forceinline__ uint32_t smem_u32(const void* p) {
    return (uint32_t)__cvta_generic_to_shared(p);
}

// ================= fp16 x2 GEMM, 128x128 tile, ldmatrix frags ==================
// C = A @ W^T + b: acc = (Ah+Al) * fp16(W). 8 warps (2m x 4n), k-step 16.
#define GST 12

struct GemmBatch {
    const float* A[3];
    const float* W[3];
    const float* bias[3];
    float*       C[3];
};

__global__ __launch_bounds__(256, 2) void gemm_f16x2_kernel(GemmBatch gb)
{
    __shared__ __align__(16) uint32_t Ahs[2][128 * GST];
    __shared__ __align__(16) uint32_t Als[2][128 * GST];
    __shared__ __align__(16) uint32_t Bhs[2][128 * GST];

    const int bz = blockIdx.z;
    const float* __restrict__ A    = gb.A[bz];
    const float* __restrict__ W    = gb.W[bz];
    const float* __restrict__ bvec = gb.bias[bz];
    float* __restrict__ C          = gb.C[bz];

    const int tid  = threadIdx.x;
    const int lane = tid & 31, wid = tid >> 5;
    const int wm   = (wid >> 2) * 64;
    const int wn   = (wid & 3) * 32;
    const int gid  = lane >> 2, tig = lane & 3;
    const int m0 = blockIdx.y * 128;
    const int n0 = blockIdx.x * 128;

    float acc[4][4][4];
#pragma unroll
    for (int mt = 0; mt < 4; mt++)
#pragma unroll
        for (int nt = 0; nt < 4; nt++)
#pragma unroll
            for (int i = 0; i < 4; i++) acc[mt][nt][i] = 0.f;

    const int frow = tid >> 1;
    const int kh   = tid & 1;
    const float* Ag = A + (size_t)(m0 + frow) * 1024 + kh * 8;
    const float* Wg = W + (size_t)(n0 + frow) * 1024 + kh * 8;

    const uint32_t aOff = ((lane & 15) * GST + (lane >> 4) * 4) * 4;
    const uint32_t bOff = ((((lane >> 4) * 8) + (lane & 7)) * GST + ((lane >> 3) & 1) * 4) * 4;

    const uint32_t sAh = smem_u32(Ahs), sAl = smem_u32(Als);
    const uint32_t sBh = smem_u32(Bhs);
    const uint32_t PBUF = 128 * GST * 4;

    float4 pa0, pa1, pw0, pw1;
    pa0 = *(const float4*)(Ag);
    pa1 = *(const float4*)(Ag + 4);
    pw0 = *(const float4*)(Wg);
    pw1 = *(const float4*)(Wg + 4);

#define GSTORE(BUF)                                                            \
    do {                                                                       \
        float h0,h1,h2,h3,h4,h5,h6,h7,l0,l1,l2,l3,l4,l5,l6,l7;                 \
        split_h(pa0.x,h0,l0); split_h(pa0.y,h1,l1);                            \
        split_h(pa0.z,h2,l2); split_h(pa0.w,h3,l3);                            \
        split_h(pa1.x,h4,l4); split_h(pa1.y,h5,l5);                            \
        split_h(pa1.z,h6,l6); split_h(pa1.w,h7,l7);                            \
        *(uint4*)&Ahs[BUF][frow*GST + kh*4] =                                  \
            make_uint4(packh(h0,h1),packh(h2,h3),packh(h4,h5),packh(h6,h7));   \
        *(uint4*)&Als[BUF][frow*GST + kh*4] =                                  \
            make_uint4(packh(l0,l1),packh(l2,l3),packh(l4,l5),packh(l6,l7));   \
        *(uint4*)&Bhs[BUF][frow*GST + kh*4] =                                  \
            make_uint4(packh(pw0.x,pw0.y),packh(pw0.z,pw0.w),                  \
                       packh(pw1.x,pw1.y),packh(pw1.z,pw1.w));                 \
    } while (0)

#define GCOMP(BUF)                                                            \
    do {                                                                      \
        uint32_t a_h[4][4], a_l[4][4], b_h[4][2];                             \
        _Pragma("unroll")                                                     \
        for (int mt = 0; mt < 4; mt++) {                                      \
            uint32_t ro = (uint32_t)((wm + mt * 16) * GST * 4);               \
            ldsm4(a_h[mt][0], a_h[mt][1], a_h[mt][2], a_h[mt][3],             \
                  sAh + (BUF) * PBUF + ro + aOff);                            \
            ldsm4(a_l[mt][0], a_l[mt][1], a_l[mt][2], a_l[mt][3],             \
                  sAl + (BUF) * PBUF + ro + aOff);                            \
        }                                                                     \
        _Pragma("unroll")                                                     \
        for (int ntp = 0; ntp < 2; ntp++) {                                   \
            uint32_t ro = (uint32_t)((wn + ntp * 16) * GST * 4);              \
            ldsm4(b_h[2*ntp][0], b_h[2*ntp][1], b_h[2*ntp+1][0], b_h[2*ntp+1][1], \
                  sBh + (BUF) * PBUF + ro + bOff);                            \
        }                                                                     \
        _Pragma("unroll")                                                     \
        for (int mt = 0; mt < 4; mt++)                                        \
            _Pragma("unroll")                                                 \
            for (int nt = 0; nt < 4; nt++) {                                  \
                mma_f16(acc[mt][nt], a_h[mt], b_h[nt]);                       \
                mma_f16(acc[mt][nt], a_l[mt], b_h[nt]);                       \
            }                                                                 \
    } while (0)

    GSTORE(0);
    __syncthreads();

    int buf = 0;
    for (int k0 = 16; k0 < 1024; k0 += 16) {
        pa0 = *(const float4*)(Ag + k0);
        pa1 = *(const float4*)(Ag + k0 + 4);
        pw0 = *(const float4*)(Wg + k0);
        pw1 = *(const float4*)(Wg + k0 + 4);
        if (buf == 0) GCOMP(0); else GCOMP(1);
        __syncthreads();
        if (buf == 0) GSTORE(1); else GSTORE(0);
        __syncthreads();
        buf ^= 1;
    }
    if (buf == 0) GCOMP(0); else GCOMP(1);

#pragma unroll
    for (int mt = 0; mt < 4; mt++) {
#pragma unroll
        for (int nt = 0; nt < 4; nt++) {
            int gm = m0 + wm + mt * 16 + gid;
            int gn = n0 + wn + nt * 8 + tig * 2;
            float b0 = __ldg(bvec + gn);
            float b1 = __ldg(bvec + gn + 1);
            *(float2*)&C[(size_t)gm * 1024 + gn] =
                make_float2(acc[mt][nt][0] + b0, acc[mt][nt][1] + b1);
            *(float2*)&C[(size_t)(gm + 8) * 1024 + gn] =
                make_float2(acc[mt][nt][2] + b0, acc[mt][nt][3] + b1);
        }
    }
}

// ================= tensor-core flash attention ==================
// QK^T: fp16 x1 (k16), scale folded into Q. P*V: fp16 x2.
#define KSTR 36    // uint32 (half2) stride per key row: (4g+t) conflict-free
#define AVSTR 72
#define PSTR 20

__global__ __launch_bounds__(256) void attn_mma_kernel(
    const float* __restrict__ Qg, const float* __restrict__ Kg,
    const float* __restrict__ Vg, float* __restrict__ CTX)
{
    __shared__ uint32_t Kw[32 * KSTR];
    __shared__ uint32_t Vh[16 * AVSTR];
    __shared__ uint32_t Ph[8][16 * PSTR];
    __shared__ uint32_t Pl[8][16 * PSTR];
    __shared__ float    Bs[32];

    const int tid  = threadIdx.x;
    const int lane = tid & 31, wid = tid >> 5;
    const int gid  = lane >> 2, tig = lane & 3;
    const int b = blockIdx.z, h = blockIdx.y;
    const int t0 = blockIdx.x * 128;

    const size_t kvBase = ((size_t)b * T_) * D_ + h * DK_;

    // Q fragments: fp16 pairs, SCALE pre-folded (exact pow2)
    uint32_t Qr[4][4];
    {
        const int r0 = t0 + wid * 16 + gid;
        const float* q0 = Qg + ((size_t)(b * T_) + r0) * D_ + h * DK_;
        const float* q1 = q0 + 8 * D_;
#pragma unroll
        for (int ks = 0; ks < 4; ks++) {
            int c = ks * 16 + 2 * tig;
            Qr[ks][0] = packh(q0[c] * SCALE_,     q0[c + 1] * SCALE_);
            Qr[ks][1] = packh(q1[c] * SCALE_,     q1[c + 1] * SCALE_);
            Qr[ks][2] = packh(q0[c + 8] * SCALE_, q0[c + 9] * SCALE_);
            Qr[ks][3] = packh(q1[c + 8] * SCALE_, q1[c + 9] * SCALE_);
        }
    }

    float oacc[8][4];
#pragma unroll
    for (int nt = 0; nt < 8; nt++)
#pragma unroll
        for (int i = 0; i < 4; i++) oacc[nt][i] = 0.f;
    float m0 = -1e30f, m1 = -1e30f, l0 = 0.f, l1 = 0.f;

    const int frow = tid >> 4;
    const int fc4  = (tid & 15) * 4;
    const float* kRow = Kg + kvBase + (size_t)frow * D_ + fc4;

    const int vp  = tid >> 4;
    const int vcg = (tid & 15) * 4;
    const float* vRow0 = Vg + kvBase + (size_t)(2 * vp) * D_ + vcg;
    const float* vRow1 = vRow0 + D_;

    float4 ka  = *(const float4*)(kRow);
    float4 kb4 = *(const float4*)(kRow + 16 * D_);
    float4 va0 = *(const float4*)(vRow0);
    float4 va1 = *(const float4*)(vRow1);

    for (int s0 = 0; s0 < T_; s0 += 32) {
        __syncthreads();
        {
            // K tile: packed half2 along d (word j = d 2j,2j+1)
            uint32_t* kw0 = &Kw[frow * KSTR + (fc4 >> 1)];
            kw0[0] = packh(ka.x, ka.y);
            kw0[1] = packh(ka.z, ka.w);
            uint32_t* kw1 = &Kw[(frow + 16) * KSTR + (fc4 >> 1)];
            kw1[0] = packh(kb4.x, kb4.y);
            kw1[1] = packh(kb4.z, kb4.w);

            uint32_t* vhp = &Vh[vp * AVSTR + vcg];
            vhp[0] = packh(va0.x, va1.x);
            vhp[1] = packh(va0.y, va1.y);
            vhp[2] = packh(va0.z, va1.z);
            vhp[3] = packh(va0.w, va1.w);

            if (tid < 32) Bs[tid] = g_bias[b * T_ + s0 + tid];
        }
        __syncthreads();

        if (s0 + 32 < T_) {
            ka  = *(const float4*)(kRow + (size_t)(s0 + 32) * D_);
            kb4 = *(const float4*)(kRow + (size_t)(s0 + 48) * D_);
            va0 = *(const float4*)(vRow0 + (size_t)(s0 + 32) * D_);
            va1 = *(const float4*)(vRow1 + (size_t)(s0 + 32) * D_);
        }

        // ---- S = (Q*scale) K^T (fp16 x1, k16) ----
        float sacc[4][4];
#pragma unroll
        for (int nt = 0; nt < 4; nt++)
#pragma unroll
            for (int i = 0; i < 4; i++) sacc[nt][i] = 0.f;
#pragma unroll
        for (int ks = 0; ks < 4; ks++) {
#pragma unroll
            for (int nt = 0; nt < 4; nt++) {
                const uint32_t* kp = &Kw[(nt * 8 + gid) * KSTR + ks * 8 + tig];
                uint32_t bh[2];
                bh[0] = kp[0];
                bh[1] = kp[4];
                mma_f16(sacc[nt], Qr[ks], bh);
            }
        }

        // ---- bias add, online softmax ----
        float sv[4][4];
#pragma unroll
        for (int nt = 0; nt < 4; nt++) {
            int c0 = nt * 8 + 2 * tig;
            float bb0 = Bs[c0], bb1 = Bs[c0 + 1];
            sv[nt][0] = sacc[nt][0] + bb0;
            sv[nt][1] = sacc[nt][1] + bb1;
            sv[nt][2] = sacc[nt][2] + bb0;
            sv[nt][3] = sacc[nt][3] + bb1;
        }
        float mx0 = fmaxf(fmaxf(sv[0][0], sv[0][1]), fmaxf(sv[1][0], sv[1][1]));
        mx0 = fmaxf(mx0, fmaxf(fmaxf(sv[2][0], sv[2][1]), fmaxf(sv[3][0], sv[3][1])));
        float mx1 = fmaxf(fmaxf(sv[0][2], sv[0][3]), fmaxf(sv[1][2], sv[1][3]));
        mx1 = fmaxf(mx1, fmaxf(fmaxf(sv[2][2], sv[2][3]), fmaxf(sv[3][2], sv[3][3])));
        mx0 = fmaxf(mx0, __shfl_xor_sync(0xffffffffu, mx0, 1));
        mx0 = fmaxf(mx0, __shfl_xor_sync(0xffffffffu, mx0, 2));
        mx1 = fmaxf(mx1, __shfl_xor_sync(0xffffffffu, mx1, 1));
        mx1 = fmaxf(mx1, __shfl_xor_sync(0xffffffffu, mx1, 2));

        float m0n = fmaxf(m0, mx0), m1n = fmaxf(m1, mx1);
        float c0f = __expf(m0 - m0n), c1f = __expf(m1 - m1n);
        m0 = m0n; m1 = m1n;

        float rs0 = 0.f, rs1 = 0.f;
#pragma unroll
        for (int nt = 0; nt < 4; nt++) {
            float p0 = __expf(sv[nt][0] - m0n);
            float p1 = __expf(sv[nt][1] - m0n);
            float p2 = __expf(sv[nt][2] - m1n);
            float p3 = __expf(sv[nt][3] - m1n);
            rs0 += p0 + p1; rs1 += p2 + p3;
            float h0, lo0, h1, lo1;
            int pi = nt * 4 + tig;
            split_h(p0, h0, lo0); split_h(p1, h1, lo1);
            Ph[wid][gid * PSTR + pi] = packh(h0, h1);
            Pl[wid][gid * PSTR + pi] = packh(lo0, lo1);
            split_h(p2, h0, lo0); split_h(p3, h1, lo1);
            Ph[wid][(gid + 8) * PSTR + pi] = packh(h0, h1);
            Pl[wid][(gid + 8) * PSTR + pi] = packh(lo0, lo1);
        }
        rs0 += __shfl_xor_sync(0xffffffffu, rs0, 1);
        rs0 += __shfl_xor_sync(0xffffffffu, rs0, 2);
        rs1 += __shfl_xor_sync(0xffffffffu, rs1, 1);
        rs1 += __shfl_xor_sync(0xffffffffu, rs1, 2);
        l0 = l0 * c0f + rs0;
        l1 = l1 * c1f + rs1;
#pragma unroll
        for (int nt = 0; nt < 8; nt++) {
            oacc[nt][0] *= c0f; oacc[nt][1] *= c0f;
            oacc[nt][2] *= c1f; oacc[nt][3] *= c1f;
        }
        __syncwarp();

        // ---- O += P V (fp16 x2: (Ph+Pl) * fp16(V)) ----
#pragma unroll
        for (int kk = 0; kk < 2; kk++) {
            uint32_t ah[4], al[4];
            ah[0] = Ph[wid][gid * PSTR + kk * 8 + tig];
            ah[1] = Ph[wid][(gid + 8) * PSTR + kk * 8 + tig];
            ah[2] = Ph[wid][gid * PSTR + kk * 8 + tig + 4];
            ah[3] = Ph[wid][(gid + 8) * PSTR + kk * 8 + tig + 4];
            al[0] = Pl[wid][gid * PSTR + kk * 8 + tig];
            al[1] = Pl[wid][(gid + 8) * PSTR + kk * 8 + tig];
            al[2] = Pl[wid][gid * PSTR + kk * 8 + tig + 4];
            al[3] = Pl[wid][(gid + 8) * PSTR + kk * 8 + tig + 4];
#pragma unroll
            for (int nt = 0; nt < 8; nt++) {
                uint32_t bh[2];
                bh[0] = Vh[(kk * 8 + tig) * AVSTR + nt * 8 + gid];
                bh[1] = Vh[(kk * 8 + tig + 4) * AVSTR + nt * 8 + gid];
                mma_f16(oacc[nt], ah, bh);
                mma_f16(oacc[nt], al, bh);
            }
        }
        __syncwarp();
    }

    float inv0 = 1.f / l0, inv1 = 1.f / l1;
    const int gr0 = t0 + wid * 16 + gid;
    float* o0 = CTX + ((size_t)(b * T_) + gr0) * D_ + h * DK_;
    float* o1 = o0 + 8 * D_;
#pragma unroll
    for (int nt = 0; nt < 8; nt++) {
        int c = nt * 8 + 2 * tig;
        *(float2*)(o0 + c) = make_float2(oacc[nt][0] * inv0, oacc[nt][1] * inv0);
        *(float2*)(o1 + c) = make_float2(oacc[nt][2] * inv1, oacc[nt][3] * inv1);
    }
}

// ---------------- launch ----------------
extern "C" void kernel_launch(void* const* d_in, const int* in_sizes, int n_in,
                              void* d_out, int out_size)
{
    const float* query = (const float*)d_in[0];
    const float* key   = (const float*)d_in[1];
    const float* value = (const float*)d_in[2];
    const void*  mask  = d_in[3];
    const float* Wq = (const float*)d_in[4];  const float* bq = (const float*)d_in[5];
    const float* Wk = (const float*)d_in[6];  const float* bk = (const float*)d_in[7];
    const float* Wv = (const float*)d_in[8];  const float* bv = (const float*)d_in[9];
    const float* Wo = (const float*)d_in[10]; const float* bo = (const float*)d_in[11];

    float *Qb, *Kb, *Vb, *Cb;
    cudaGetSymbolAddress((void**)&Qb, g_Q);
    cudaGetSymbolAddress((void**)&Kb, g_K);
    cudaGetSymbolAddress((void**)&Vb, g_V);
    cudaGetSymbolAddress((void**)&Cb, g_CTX);

    detect_mask_kernel<<<1, 256>>>((const unsigned int*)mask);
    build_bias_kernel<<<(M_ + 255) / 256, 256>>>(mask);

    GemmBatch gqkv;
    gqkv.A[0] = query; gqkv.A[1] = key; gqkv.A[2] = value;
    gqkv.W[0] = Wq;    gqkv.W[1] = Wk;  gqkv.W[2] = Wv;
    gqkv.bias[0] = bq; gqkv.bias[1] = bk; gqkv.bias[2] = bv;
    gqkv.C[0] = Qb;    gqkv.C[1] = Kb;  gqkv.C[2] = Vb;
    gemm_f16x2_kernel<<<dim3(D_ / 128, M_ / 128, 3), 256>>>(gqkv);

    attn_mma_kernel<<<dim3(T_ / 128, H_, B_), 256>>>(Qb, Kb, Vb, Cb);

    GemmBatch go;
    go.A[0] = Cb; go.A[1] = Cb; go.A[2] = Cb;
    go.W[0] = Wo; go.W[1] = Wo; go.W[2] = Wo;
    go.bias[0] = bo; go.bias[1] = bo; go.bias[2] = bo;
    go.C[0] = (float*)d_out; go.C[1] = (float*)d_out; go.C[2] = (float*)d_out;
    gemm_f16x2_kernel<<<dim3(D_ / 128, M_ / 128, 1), 256>>>(go);
}

// round 14
// speedup vs baseline: 1.7144x; 1.0985x over previous
#include <cuda_runtime.h>
#include <cuda_fp16.h>
#include <cstdint>

#define B_ 2
#define T_ 2048
#define D_ 1024
#define H_ 16
#define DK_ 64
#define M_ (B_*T_)
#define SCALE_ 0.125f
#define QSCALE_ 0.1803368801111144f   // SCALE_ * log2(e)

// ---------------- scratch ----------------
__device__ float g_Q[M_*D_];
__device__ float g_K[M_*D_];
__device__ float g_V[M_*D_];
__device__ float g_CTX[M_*D_];
__device__ float g_bias[M_];
__device__ int   g_maskmode;

// ---------------- mask dtype detection ----------------
__global__ void detect_mask_kernel(const unsigned int* __restrict__ w) {
    __shared__ int s_badint, s_badfloat;
    if (threadIdx.x == 0) { s_badint = 0; s_badfloat = 0; }
    __syncthreads();
    int bi = 0, bf = 0;
    for (int i = threadIdx.x; i < 1024; i += blockDim.x) {
        unsigned v = w[i];
        if (v > 1u) bi = 1;
        if (v != 0u && v != 0x3F800000u) bf = 1;
    }
    if (bi) atomicOr(&s_badint, 1);
    if (bf) atomicOr(&s_badfloat, 1);
    __syncthreads();
    if (threadIdx.x == 0)
        g_maskmode = (!s_badint) ? 0 : ((!s_badfloat) ? 1 : 2);
}

__global__ void build_bias_kernel(const void* __restrict__ mask) {
    int i = blockIdx.x * blockDim.x + threadIdx.x;
    if (i >= M_) return;
    int mode = g_maskmode;
    bool keep;
    if (mode == 0)      keep = ((const int*)mask)[i] != 0;
    else if (mode == 1) keep = ((const float*)mask)[i] != 0.0f;
    else                keep = ((const unsigned char*)mask)[i] != 0;
    g_bias[i] = keep ? 0.0f : -1e30f;
}

// ---------------- mma / ldmatrix helpers ----------------
__device__ __forceinline__ void mma_f16(float* d, const uint32_t* a, const uint32_t* b) {
    asm volatile(
        "mma.sync.aligned.m16n8k16.row.col.f32.f16.f16.f32 "
        "{%0,%1,%2,%3}, {%4,%5,%6,%7}, {%8,%9}, {%0,%1,%2,%3};"
        : "+f"(d[0]), "+f"(d[1]), "+f"(d[2]), "+f"(d[3])
        : "r"(a[0]), "r"(a[1]), "r"(a[2]), "r"(a[3]), "r"(b[0]), "r"(b[1]));
}

__device__ __forceinline__ void ldsm4(uint32_t& r0, uint32_t& r1, uint32_t& r2, uint32_t& r3,
                                      uint32_t saddr) {
    asm volatile("ldmatrix.sync.aligned.m8n8.x4.shared.b16 {%0,%1,%2,%3}, [%4];"
                 : "=r"(r0), "=r"(r1), "=r"(r2), "=r"(r3) : "r"(saddr));
}

__device__ __forceinline__ void split_h(float x, float& h, float& l) {
    h = __half2float(__float2half_rn(x));
    l = x - h;
}

__device__ __forceinline__ uint32_t packh(float a, float b) {
    __half2 t = __floats2half2_rn(a, b);   // low half = a (even k)
    return *reinterpret_cast<uint32_t*>(&t);
}

__device__ __forceinline__ uint32_t smem_u32(const void* p) {
    return (uint32_t)__cvta_generic_to_shared(p);
}

// ================= fp16 x2 GEMM, 128x128 tile, ldmatrix frags ==================
// C = A @ W^T + b: acc = (Ah+Al) * fp16(W). 8 warps (2m x 4n), k-step 16.
#define GST 12

struct GemmBatch {
    const float* A[3];
    const float* W[3];
    const float* bias[3];
    float*       C[3];
};

__global__ __launch_bounds__(256, 2) void gemm_f16x2_kernel(GemmBatch gb)
{
    __shared__ __align__(16) uint32_t Ahs[2][128 * GST];
    __shared__ __align__(16) uint32_t Als[2][128 * GST];
    __shared__ __align__(16) uint32_t Bhs[2][128 * GST];

    const int bz = blockIdx.z;
    const float* __restrict__ A    = gb.A[bz];
    const float* __restrict__ W    = gb.W[bz];
    const float* __restrict__ bvec = gb.bias[bz];
    float* __restrict__ C          = gb.C[bz];

    const int tid  = threadIdx.x;
    const int lane = tid & 31, wid = tid >> 5;
    const int wm   = (wid >> 2) * 64;
    const int wn   = (wid & 3) * 32;
    const int gid  = lane >> 2, tig = lane & 3;
    const int m0 = blockIdx.y * 128;
    const int n0 = blockIdx.x * 128;

    float acc[4][4][4];
#pragma unroll
    for (int mt = 0; mt < 4; mt++)
#pragma unroll
        for (int nt = 0; nt < 4; nt++)
#pragma unroll
            for (int i = 0; i < 4; i++) acc[mt][nt][i] = 0.f;

    const int frow = tid >> 1;
    const int kh   = tid & 1;
    const float* Ag = A + (size_t)(m0 + frow) * 1024 + kh * 8;
    const float* Wg = W + (size_t)(n0 + frow) * 1024 + kh * 8;

    const uint32_t aOff = ((lane & 15) * GST + (lane >> 4) * 4) * 4;
    const uint32_t bOff = ((((lane >> 4) * 8) + (lane & 7)) * GST + ((lane >> 3) & 1) * 4) * 4;

    const uint32_t sAh = smem_u32(Ahs), sAl = smem_u32(Als);
    const uint32_t sBh = smem_u32(Bhs);
    const uint32_t PBUF = 128 * GST * 4;

    float4 pa0, pa1, pw0, pw1;
    pa0 = *(const float4*)(Ag);
    pa1 = *(const float4*)(Ag + 4);
    pw0 = *(const float4*)(Wg);
    pw1 = *(const float4*)(Wg + 4);

#define GSTORE(BUF)                                                            \
    do {                                                                       \
        float h0,h1,h2,h3,h4,h5,h6,h7,l0,l1,l2,l3,l4,l5,l6,l7;                 \
        split_h(pa0.x,h0,l0); split_h(pa0.y,h1,l1);                            \
        split_h(pa0.z,h2,l2); split_h(pa0.w,h3,l3);                            \
        split_h(pa1.x,h4,l4); split_h(pa1.y,h5,l5);                            \
        split_h(pa1.z,h6,l6); split_h(pa1.w,h7,l7);                            \
        *(uint4*)&Ahs[BUF][frow*GST + kh*4] =                                  \
            make_uint4(packh(h0,h1),packh(h2,h3),packh(h4,h5),packh(h6,h7));   \
        *(uint4*)&Als[BUF][frow*GST + kh*4] =                                  \
            make_uint4(packh(l0,l1),packh(l2,l3),packh(l4,l5),packh(l6,l7));   \
        *(uint4*)&Bhs[BUF][frow*GST + kh*4] =                                  \
            make_uint4(packh(pw0.x,pw0.y),packh(pw0.z,pw0.w),                  \
                       packh(pw1.x,pw1.y),packh(pw1.z,pw1.w));                 \
    } while (0)

#define GCOMP(BUF)                                                            \
    do {                                                                      \
        uint32_t a_h[4][4], a_l[4][4], b_h[4][2];                             \
        _Pragma("unroll")                                                     \
        for (int mt = 0; mt < 4; mt++) {                                      \
            uint32_t ro = (uint32_t)((wm + mt * 16) * GST * 4);               \
            ldsm4(a_h[mt][0], a_h[mt][1], a_h[mt][2], a_h[mt][3],             \
                  sAh + (BUF) * PBUF + ro + aOff);                            \
            ldsm4(a_l[mt][0], a_l[mt][1], a_l[mt][2], a_l[mt][3],             \
                  sAl + (BUF) * PBUF + ro + aOff);                            \
        }                                                                     \
        _Pragma("unroll")                                                     \
        for (int ntp = 0; ntp < 2; ntp++) {                                   \
            uint32_t ro = (uint32_t)((wn + ntp * 16) * GST * 4);              \
            ldsm4(b_h[2*ntp][0], b_h[2*ntp][1], b_h[2*ntp+1][0], b_h[2*ntp+1][1], \
                  sBh + (BUF) * PBUF + ro + bOff);                            \
        }                                                                     \
        _Pragma("unroll")                                                     \
        for (int mt = 0; mt < 4; mt++)                                        \
            _Pragma("unroll")                                                 \
            for (int nt = 0; nt < 4; nt++) {                                  \
                mma_f16(acc[mt][nt], a_h[mt], b_h[nt]);                       \
                mma_f16(acc[mt][nt], a_l[mt], b_h[nt]);                       \
            }                                                                 \
    } while (0)

    GSTORE(0);
    __syncthreads();

    int buf = 0;
    for (int k0 = 16; k0 < 1024; k0 += 16) {
        pa0 = *(const float4*)(Ag + k0);
        pa1 = *(const float4*)(Ag + k0 + 4);
        pw0 = *(const float4*)(Wg + k0);
        pw1 = *(const float4*)(Wg + k0 + 4);
        if (buf == 0) GCOMP(0); else GCOMP(1);
        __syncthreads();
        if (buf == 0) GSTORE(1); else GSTORE(0);
        __syncthreads();
        buf ^= 1;
    }
    if (buf == 0) GCOMP(0); else GCOMP(1);

#pragma unroll
    for (int mt = 0; mt < 4; mt++) {
#pragma unroll
        for (int nt = 0; nt < 4; nt++) {
            int gm = m0 + wm + mt * 16 + gid;
            int gn = n0 + wn + nt * 8 + tig * 2;
            float b0 = __ldg(bvec + gn);
            float b1 = __ldg(bvec + gn + 1);
            *(float2*)&C[(size_t)gm * 1024 + gn] =
                make_float2(acc[mt][nt][0] + b0, acc[mt][nt][1] + b1);
            *(float2*)&C[(size_t)(gm + 8) * 1024 + gn] =
                make_float2(acc[mt][nt][2] + b0, acc[mt][nt][3] + b1);
        }
    }
}

// ================= tensor-core flash attention ==================
// QK^T: fp16 x1 (k16), SCALE*log2e folded into Q; softmax in exp2 domain.
// P*V: fp16 x1 — P rounded to a single fp16 plane.
#define KSTR 36    // uint32 (half2) stride per key row: (4g+t) conflict-free
#define AVSTR 72
#define PSTR 20

__global__ __launch_bounds__(256) void attn_mma_kernel(
    const float* __restrict__ Qg, const float* __restrict__ Kg,
    const float* __restrict__ Vg, float* __restrict__ CTX)
{
    __shared__ uint32_t Kw[32 * KSTR];
    __shared__ uint32_t Vh[16 * AVSTR];
    __shared__ uint32_t Ph[8][16 * PSTR];
    __shared__ float    Bs[32];

    const int tid  = threadIdx.x;
    const int lane = tid & 31, wid = tid >> 5;
    const int gid  = lane >> 2, tig = lane & 3;
    const int b = blockIdx.z, h = blockIdx.y;
    const int t0 = blockIdx.x * 128;

    const size_t kvBase = ((size_t)b * T_) * D_ + h * DK_;

    // Q fragments: fp16 pairs, SCALE*log2e pre-folded
    uint32_t Qr[4][4];
    {
        const int r0 = t0 + wid * 16 + gid;
        const float* q0 = Qg + ((size_t)(b * T_) + r0) * D_ + h * DK_;
        const float* q1 = q0 + 8 * D_;
#pragma unroll
        for (int ks = 0; ks < 4; ks++) {
            int c = ks * 16 + 2 * tig;
            Qr[ks][0] = packh(q0[c] * QSCALE_,     q0[c + 1] * QSCALE_);
            Qr[ks][1] = packh(q1[c] * QSCALE_,     q1[c + 1] * QSCALE_);
            Qr[ks][2] = packh(q0[c + 8] * QSCALE_, q0[c + 9] * QSCALE_);
            Qr[ks][3] = packh(q1[c + 8] * QSCALE_, q1[c + 9] * QSCALE_);
        }
    }

    float oacc[8][4];
#pragma unroll
    for (int nt = 0; nt < 8; nt++)
#pragma unroll
        for (int i = 0; i < 4; i++) oacc[nt][i] = 0.f;
    float m0 = -1e30f, m1 = -1e30f, l0 = 0.f, l1 = 0.f;

    const int frow = tid >> 4;
    const int fc4  = (tid & 15) * 4;
    const float* kRow = Kg + kvBase + (size_t)frow * D_ + fc4;

    const int vp  = tid >> 4;
    const int vcg = (tid & 15) * 4;
    const float* vRow0 = Vg + kvBase + (size_t)(2 * vp) * D_ + vcg;
    const float* vRow1 = vRow0 + D_;

    float4 ka  = *(const float4*)(kRow);
    float4 kb4 = *(const float4*)(kRow + 16 * D_);
    float4 va0 = *(const float4*)(vRow0);
    float4 va1 = *(const float4*)(vRow1);

    for (int s0 = 0; s0 < T_; s0 += 32) {
        __syncthreads();
        {
            uint32_t* kw0 = &Kw[frow * KSTR + (fc4 >> 1)];
            kw0[0] = packh(ka.x, ka.y);
            kw0[1] = packh(ka.z, ka.w);
            uint32_t* kw1 = &Kw[(frow + 16) * KSTR + (fc4 >> 1)];
            kw1[0] = packh(kb4.x, kb4.y);
            kw1[1] = packh(kb4.z, kb4.w);

            uint32_t* vhp = &Vh[vp * AVSTR + vcg];
            vhp[0] = packh(va0.x, va1.x);
            vhp[1] = packh(va0.y, va1.y);
            vhp[2] = packh(va0.z, va1.z);
            vhp[3] = packh(va0.w, va1.w);

            if (tid < 32) Bs[tid] = g_bias[b * T_ + s0 + tid];
        }
        __syncthreads();

        if (s0 + 32 < T_) {
            ka  = *(const float4*)(kRow + (size_t)(s0 + 32) * D_);
            kb4 = *(const float4*)(kRow + (size_t)(s0 + 48) * D_);
            va0 = *(const float4*)(vRow0 + (size_t)(s0 + 32) * D_);
            va1 = *(const float4*)(vRow1 + (size_t)(s0 + 32) * D_);
        }

        // ---- S = (Q*scale*log2e) K^T (fp16 x1, k16) ----
        float sacc[4][4];
#pragma unroll
        for (int nt = 0; nt < 4; nt++)
#pragma unroll
            for (int i = 0; i < 4; i++) sacc[nt][i] = 0.f;
#pragma unroll
        for (int ks = 0; ks < 4; ks++) {
#pragma unroll
            for (int nt = 0; nt < 4; nt++) {
                const uint32_t* kp = &Kw[(nt * 8 + gid) * KSTR + ks * 8 + tig];
                uint32_t bh[2];
                bh[0] = kp[0];
                bh[1] = kp[4];
                mma_f16(sacc[nt], Qr[ks], bh);
            }
        }

        // ---- bias add, online softmax (exp2 domain) ----
        float sv[4][4];
#pragma unroll
        for (int nt = 0; nt < 4; nt++) {
            int c0 = nt * 8 + 2 * tig;
            float bb0 = Bs[c0], bb1 = Bs[c0 + 1];
            sv[nt][0] = sacc[nt][0] + bb0;
            sv[nt][1] = sacc[nt][1] + bb1;
            sv[nt][2] = sacc[nt][2] + bb0;
            sv[nt][3] = sacc[nt][3] + bb1;
        }
        float mx0 = fmaxf(fmaxf(sv[0][0], sv[0][1]), fmaxf(sv[1][0], sv[1][1]));
        mx0 = fmaxf(mx0, fmaxf(fmaxf(sv[2][0], sv[2][1]), fmaxf(sv[3][0], sv[3][1])));
        float mx1 = fmaxf(fmaxf(sv[0][2], sv[0][3]), fmaxf(sv[1][2], sv[1][3]));
        mx1 = fmaxf(mx1, fmaxf(fmaxf(sv[2][2], sv[2][3]), fmaxf(sv[3][2], sv[3][3])));
        mx0 = fmaxf(mx0, __shfl_xor_sync(0xffffffffu, mx0, 1));
        mx0 = fmaxf(mx0, __shfl_xor_sync(0xffffffffu, mx0, 2));
        mx1 = fmaxf(mx1, __shfl_xor_sync(0xffffffffu, mx1, 1));
        mx1 = fmaxf(mx1, __shfl_xor_sync(0xffffffffu, mx1, 2));

        float m0n = fmaxf(m0, mx0), m1n = fmaxf(m1, mx1);
        float c0f = exp2f(m0 - m0n), c1f = exp2f(m1 - m1n);
        m0 = m0n; m1 = m1n;

        float rs0 = 0.f, rs1 = 0.f;
#pragma unroll
        for (int nt = 0; nt < 4; nt++) {
            float p0 = exp2f(sv[nt][0] - m0n);
            float p1 = exp2f(sv[nt][1] - m0n);
            float p2 = exp2f(sv[nt][2] - m1n);
            float p3 = exp2f(sv[nt][3] - m1n);
            rs0 += p0 + p1; rs1 += p2 + p3;
            int pi = nt * 4 + tig;
            Ph[wid][gid * PSTR + pi]       = packh(p0, p1);
            Ph[wid][(gid + 8) * PSTR + pi] = packh(p2, p3);
        }
        rs0 += __shfl_xor_sync(0xffffffffu, rs0, 1);
        rs0 += __shfl_xor_sync(0xffffffffu, rs0, 2);
        rs1 += __shfl_xor_sync(0xffffffffu, rs1, 1);
        rs1 += __shfl_xor_sync(0xffffffffu, rs1, 2);
        l0 = l0 * c0f + rs0;
        l1 = l1 * c1f + rs1;
#pragma unroll
        for (int nt = 0; nt < 8; nt++) {
            oacc[nt][0] *= c0f; oacc[nt][1] *= c0f;
            oacc[nt][2] *= c1f; oacc[nt][3] *= c1f;
        }
        __syncwarp();

        // ---- O += P V (fp16 x1) ----
#pragma unroll
        for (int kk = 0; kk < 2; kk++) {
            uint32_t ah[4];
            ah[0] = Ph[wid][gid * PSTR + kk * 8 + tig];
            ah[1] = Ph[wid][(gid + 8) * PSTR + kk * 8 + tig];
            ah[2] = Ph[wid][gid * PSTR + kk * 8 + tig + 4];
            ah[3] = Ph[wid][(gid + 8) * PSTR + kk * 8 + tig + 4];
#pragma unroll
            for (int nt = 0; nt < 8; nt++) {
                uint32_t bh[2];
                bh[0] = Vh[(kk * 8 + tig) * AVSTR + nt * 8 + gid];
                bh[1] = Vh[(kk * 8 + tig + 4) * AVSTR + nt * 8 + gid];
                mma_f16(oacc[nt], ah, bh);
            }
        }
        __syncwarp();
    }

    float inv0 = 1.f / l0, inv1 = 1.f / l1;
    const int gr0 = t0 + wid * 16 + gid;
    float* o0 = CTX + ((size_t)(b * T_) + gr0) * D_ + h * DK_;
    float* o1 = o0 + 8 * D_;
#pragma unroll
    for (int nt = 0; nt < 8; nt++) {
        int c = nt * 8 + 2 * tig;
        *(float2*)(o0 + c) = make_float2(oacc[nt][0] * inv0, oacc[nt][1] * inv0);
        *(float2*)(o1 + c) = make_float2(oacc[nt][2] * inv1, oacc[nt][3] * inv1);
    }
}

// ---------------- launch ----------------
extern "C" void kernel_launch(void* const* d_in, const int* in_sizes, int n_in,
                              void* d_out, int out_size)
{
    const float* query = (const float*)d_in[0];
    const float* key   = (const float*)d_in[1];
    const float* value = (const float*)d_in[2];
    const void*  mask  = d_in[3];
    const float* Wq = (const float*)d_in[4];  const float* bq = (const float*)d_in[5];
    const float* Wk = (const float*)d_in[6];  const float* bk = (const float*)d_in[7];
    const float* Wv = (const float*)d_in[8];  const float* bv = (const float*)d_in[9];
    const float* Wo = (const float*)d_in[10]; const float* bo = (const float*)d_in[11];

    float *Qb, *Kb, *Vb, *Cb;
    cudaGetSymbolAddress((void**)&Qb, g_Q);
    cudaGetSymbolAddress((void**)&Kb, g_K);
    cudaGetSymbolAddress((void**)&Vb, g_V);
    cudaGetSymbolAddress((void**)&Cb, g_CTX);

    detect_mask_kernel<<<1, 256>>>((const unsigned int*)mask);
    build_bias_kernel<<<(M_ + 255) / 256, 256>>>(mask);

    GemmBatch gqkv;
    gqkv.A[0] = query; gqkv.A[1] = key; gqkv.A[2] = value;
    gqkv.W[0] = Wq;    gqkv.W[1] = Wk;  gqkv.W[2] = Wv;
    gqkv.bias[0] = bq; gqkv.bias[1] = bk; gqkv.bias[2] = bv;
    gqkv.C[0] = Qb;    gqkv.C[1] = Kb;  gqkv.C[2] = Vb;
    gemm_f16x2_kernel<<<dim3(D_ / 128, M_ / 128, 3), 256>>>(gqkv);

    attn_mma_kernel<<<dim3(T_ / 128, H_, B_), 256>>>(Qb, Kb, Vb, Cb);

    GemmBatch go;
    go.A[0] = Cb; go.A[1] = Cb; go.A[2] = Cb;
    go.W[0] = Wo; go.W[1] = Wo; go.W[2] = Wo;
    go.bias[0] = bo; go.bias[1] = bo; go.bias[2] = bo;
    go.C[0] = (float*)d_out; go.C[1] = (float*)d_out; go.C[2] = (float*)d_out;
    gemm_f16x2_kernel<<<dim3(D_ / 128, M_ / 128, 1), 256>>>(go);
}

// round 15
// speedup vs baseline: 1.7787x; 1.0375x over previous
#include <cuda_runtime.h>
#include <cuda_fp16.h>
#include <cstdint>

#define B_ 2
#define T_ 2048
#define D_ 1024
#define H_ 16
#define DK_ 64
#define M_ (B_*T_)
#define SCALE_ 0.125f
#define QSCALE_ 0.1803368801111144f   // SCALE_ * log2(e)

// ---------------- scratch ----------------
__device__ float g_Q[M_*D_];
__device__ float g_K[M_*D_];
__device__ float g_V[M_*D_];
__device__ float g_CTX[M_*D_];
__device__ float g_bias[M_];
__device__ int   g_maskmode;

// ---------------- mask dtype detection ----------------
__global__ void detect_mask_kernel(const unsigned int* __restrict__ w) {
    __shared__ int s_badint, s_badfloat;
    if (threadIdx.x == 0) { s_badint = 0; s_badfloat = 0; }
    __syncthreads();
    int bi = 0, bf = 0;
    for (int i = threadIdx.x; i < 1024; i += blockDim.x) {
        unsigned v = w[i];
        if (v > 1u) bi = 1;
        if (v != 0u && v != 0x3F800000u) bf = 1;
    }
    if (bi) atomicOr(&s_badint, 1);
    if (bf) atomicOr(&s_badfloat, 1);
    __syncthreads();
    if (threadIdx.x == 0)
        g_maskmode = (!s_badint) ? 0 : ((!s_badfloat) ? 1 : 2);
}

__global__ void build_bias_kernel(const void* __restrict__ mask) {
    int i = blockIdx.x * blockDim.x + threadIdx.x;
    if (i >= M_) return;
    int mode = g_maskmode;
    bool keep;
    if (mode == 0)      keep = ((const int*)mask)[i] != 0;
    else if (mode == 1) keep = ((const float*)mask)[i] != 0.0f;
    else                keep = ((const unsigned char*)mask)[i] != 0;
    g_bias[i] = keep ? 0.0f : -1e30f;
}

// ---------------- mma / ldmatrix helpers ----------------
__device__ __forceinline__ void mma_f16(float* d, const uint32_t* a, const uint32_t* b) {
    asm volatile(
        "mma.sync.aligned.m16n8k16.row.col.f32.f16.f16.f32 "
        "{%0,%1,%2,%3}, {%4,%5,%6,%7}, {%8,%9}, {%0,%1,%2,%3};"
        : "+f"(d[0]), "+f"(d[1]), "+f"(d[2]), "+f"(d[3])
        : "r"(a[0]), "r"(a[1]), "r"(a[2]), "r"(a[3]), "r"(b[0]), "r"(b[1]));
}

__device__ __forceinline__ void ldsm4(uint32_t& r0, uint32_t& r1, uint32_t& r2, uint32_t& r3,
                                      uint32_t saddr) {
    asm volatile("ldmatrix.sync.aligned.m8n8.x4.shared.b16 {%0,%1,%2,%3}, [%4];"
                 : "=r"(r0), "=r"(r1), "=r"(r2), "=r"(r3) : "r"(saddr));
}

__device__ __forceinline__ void split_h(float x, float& h, float& l) {
    h = __half2float(__float2half_rn(x));
    l = x - h;
}

__device__ __forceinline__ uint32_t packh(float a, float b) {
    __half2 t = __floats2half2_rn(a, b);   // low half = a (even k)
    return *reinterpret_cast<uint32_t*>(&t);
}

__device__ __forceinline__ uint32_t smem_u32(const void* p) {
    return (uint32_t)__cvta_generic_to_shared(p);
}

// ================= fp16 x2 GEMM, 128x128 tile, ldmatrix frags ==================
// C = A @ W^T + b: acc = (Ah+Al) * fp16(W). 8 warps (2m x 4n), k-step 16.
#define GST 12

struct GemmBatch {
    const float* A[3];
    const float* W[3];
    const float* bias[3];
    float*       C[3];
};

__global__ __launch_bounds__(256, 2) void gemm_f16x2_kernel(GemmBatch gb)
{
    __shared__ __align__(16) uint32_t Ahs[2][128 * GST];
    __shared__ __align__(16) uint32_t Als[2][128 * GST];
    __shared__ __align__(16) uint32_t Bhs[2][128 * GST];

    const int bz = blockIdx.z;
    const float* __restrict__ A    = gb.A[bz];
    const float* __restrict__ W    = gb.W[bz];
    const float* __restrict__ bvec = gb.bias[bz];
    float* __restrict__ C          = gb.C[bz];

    const int tid  = threadIdx.x;
    const int lane = tid & 31, wid = tid >> 5;
    const int wm   = (wid >> 2) * 64;
    const int wn   = (wid & 3) * 32;
    const int gid  = lane >> 2, tig = lane & 3;
    const int m0 = blockIdx.y * 128;
    const int n0 = blockIdx.x * 128;

    float acc[4][4][4];
#pragma unroll
    for (int mt = 0; mt < 4; mt++)
#pragma unroll
        for (int nt = 0; nt < 4; nt++)
#pragma unroll
            for (int i = 0; i < 4; i++) acc[mt][nt][i] = 0.f;

    const int frow = tid >> 1;
    const int kh   = tid & 1;
    const float* Ag = A + (size_t)(m0 + frow) * 1024 + kh * 8;
    const float* Wg = W + (size_t)(n0 + frow) * 1024 + kh * 8;

    const uint32_t aOff = ((lane & 15) * GST + (lane >> 4) * 4) * 4;
    const uint32_t bOff = ((((lane >> 4) * 8) + (lane & 7)) * GST + ((lane >> 3) & 1) * 4) * 4;

    const uint32_t sAh = smem_u32(Ahs), sAl = smem_u32(Als);
    const uint32_t sBh = smem_u32(Bhs);
    const uint32_t PBUF = 128 * GST * 4;

    float4 pa0, pa1, pw0, pw1;
    pa0 = *(const float4*)(Ag);
    pa1 = *(const float4*)(Ag + 4);
    pw0 = *(const float4*)(Wg);
    pw1 = *(const float4*)(Wg + 4);

#define GSTORE(BUF)                                                            \
    do {                                                                       \
        float h0,h1,h2,h3,h4,h5,h6,h7,l0,l1,l2,l3,l4,l5,l6,l7;                 \
        split_h(pa0.x,h0,l0); split_h(pa0.y,h1,l1);                            \
        split_h(pa0.z,h2,l2); split_h(pa0.w,h3,l3);                            \
        split_h(pa1.x,h4,l4); split_h(pa1.y,h5,l5);                            \
        split_h(pa1.z,h6,l6); split_h(pa1.w,h7,l7);                            \
        *(uint4*)&Ahs[BUF][frow*GST + kh*4] =                                  \
            make_uint4(packh(h0,h1),packh(h2,h3),packh(h4,h5),packh(h6,h7));   \
        *(uint4*)&Als[BUF][frow*GST + kh*4] =                                  \
            make_uint4(packh(l0,l1),packh(l2,l3),packh(l4,l5),packh(l6,l7));   \
        *(uint4*)&Bhs[BUF][frow*GST + kh*4] =                                  \
            make_uint4(packh(pw0.x,pw0.y),packh(pw0.z,pw0.w),                  \
                       packh(pw1.x,pw1.y),packh(pw1.z,pw1.w));                 \
    } while (0)

#define GCOMP(BUF)                                                            \
    do {                                                                      \
        uint32_t a_h[4][4], a_l[4][4], b_h[4][2];                             \
        _Pragma("unroll")                                                     \
        for (int mt = 0; mt < 4; mt++) {                                      \
            uint32_t ro = (uint32_t)((wm + mt * 16) * GST * 4);               \
            ldsm4(a_h[mt][0], a_h[mt][1], a_h[mt][2], a_h[mt][3],             \
                  sAh + (BUF) * PBUF + ro + aOff);                            \
            ldsm4(a_l[mt][0], a_l[mt][1], a_l[mt][2], a_l[mt][3],             \
                  sAl + (BUF) * PBUF + ro + aOff);                            \
        }                                                                     \
        _Pragma("unroll")                                                     \
        for (int ntp = 0; ntp < 2; ntp++) {                                   \
            uint32_t ro = (uint32_t)((wn + ntp * 16) * GST * 4);              \
            ldsm4(b_h[2*ntp][0], b_h[2*ntp][1], b_h[2*ntp+1][0], b_h[2*ntp+1][1], \
                  sBh + (BUF) * PBUF + ro + bOff);                            \
        }                                                                     \
        _Pragma("unroll")                                                     \
        for (int mt = 0; mt < 4; mt++)                                        \
            _Pragma("unroll")                                                 \
            for (int nt = 0; nt < 4; nt++) {                                  \
                mma_f16(acc[mt][nt], a_h[mt], b_h[nt]);                       \
                mma_f16(acc[mt][nt], a_l[mt], b_h[nt]);                       \
            }                                                                 \
    } while (0)

    GSTORE(0);
    __syncthreads();

    int buf = 0;
    for (int k0 = 16; k0 < 1024; k0 += 16) {
        pa0 = *(const float4*)(Ag + k0);
        pa1 = *(const float4*)(Ag + k0 + 4);
        pw0 = *(const float4*)(Wg + k0);
        pw1 = *(const float4*)(Wg + k0 + 4);
        if (buf == 0) GCOMP(0); else GCOMP(1);
        __syncthreads();
        if (buf == 0) GSTORE(1); else GSTORE(0);
        __syncthreads();
        buf ^= 1;
    }
    if (buf == 0) GCOMP(0); else GCOMP(1);

#pragma unroll
    for (int mt = 0; mt < 4; mt++) {
#pragma unroll
        for (int nt = 0; nt < 4; nt++) {
            int gm = m0 + wm + mt * 16 + gid;
            int gn = n0 + wn + nt * 8 + tig * 2;
            float b0 = __ldg(bvec + gn);
            float b1 = __ldg(bvec + gn + 1);
            *(float2*)&C[(size_t)gm * 1024 + gn] =
                make_float2(acc[mt][nt][0] + b0, acc[mt][nt][1] + b1);
            *(float2*)&C[(size_t)(gm + 8) * 1024 + gn] =
                make_float2(acc[mt][nt][2] + b0, acc[mt][nt][3] + b1);
        }
    }
}

// ================= tensor-core flash attention ==================
// QK^T: fp16 x1 (k16), SCALE*log2e folded into Q; exp2 softmax.
// P*V: fp16 x1, P built DIRECTLY from S C-fragments in registers (no smem trip).
// K stored pair-permuted (w<4 -> 2w else 2w-7 within each 8-word chunk) so the
// B-fragment pair (tig, tig+4) is one LDS.64. KSTR=40 words: row stride = 8 mod 32
// -> conflict-free 64-bit loads.
#define KSTR 40
#define AVSTR 72

__global__ __launch_bounds__(256) void attn_mma_kernel(
    const float* __restrict__ Qg, const float* __restrict__ Kg,
    const float* __restrict__ Vg, float* __restrict__ CTX)
{
    __shared__ __align__(16) uint32_t Kw[32 * KSTR];
    __shared__ uint32_t Vh[16 * AVSTR];
    __shared__ float    Bs[32];

    const int tid  = threadIdx.x;
    const int lane = tid & 31, wid = tid >> 5;
    const int gid  = lane >> 2, tig = lane & 3;
    const int b = blockIdx.z, h = blockIdx.y;
    const int t0 = blockIdx.x * 128;

    const size_t kvBase = ((size_t)b * T_) * D_ + h * DK_;

    // Q fragments: fp16 pairs, SCALE*log2e pre-folded
    uint32_t Qr[4][4];
    {
        const int r0 = t0 + wid * 16 + gid;
        const float* q0 = Qg + ((size_t)(b * T_) + r0) * D_ + h * DK_;
        const float* q1 = q0 + 8 * D_;
#pragma unroll
        for (int ks = 0; ks < 4; ks++) {
            int c = ks * 16 + 2 * tig;
            Qr[ks][0] = packh(q0[c] * QSCALE_,     q0[c + 1] * QSCALE_);
            Qr[ks][1] = packh(q1[c] * QSCALE_,     q1[c + 1] * QSCALE_);
            Qr[ks][2] = packh(q0[c + 8] * QSCALE_, q0[c + 9] * QSCALE_);
            Qr[ks][3] = packh(q1[c + 8] * QSCALE_, q1[c + 9] * QSCALE_);
        }
    }

    float oacc[8][4];
#pragma unroll
    for (int nt = 0; nt < 8; nt++)
#pragma unroll
        for (int i = 0; i < 4; i++) oacc[nt][i] = 0.f;
    float m0 = -1e30f, m1 = -1e30f, l0 = 0.f, l1 = 0.f;

    const int frow = tid >> 4;
    const int fc4  = (tid & 15) * 4;
    const float* kRow = Kg + kvBase + (size_t)frow * D_ + fc4;

    const int vp  = tid >> 4;
    const int vcg = (tid & 15) * 4;
    const float* vRow0 = Vg + kvBase + (size_t)(2 * vp) * D_ + vcg;
    const float* vRow1 = vRow0 + D_;

    // permuted word positions for K fill: word j (d=2j..2j+1), j even, and j+1
    const int jw = fc4 >> 1;                        // even, 0..30
    const int w0 = jw & 7, w1 = (jw + 1) & 7;
    const int kp0 = (jw & ~7) + ((w0 < 4) ? 2 * w0 : 2 * w0 - 7);
    const int kp1 = (jw & ~7) + ((w1 < 4) ? 2 * w1 : 2 * w1 - 7);

    float4 ka  = *(const float4*)(kRow);
    float4 kb4 = *(const float4*)(kRow + 16 * D_);
    float4 va0 = *(const float4*)(vRow0);
    float4 va1 = *(const float4*)(vRow1);

    for (int s0 = 0; s0 < T_; s0 += 32) {
        __syncthreads();
        {
            uint32_t* kr0 = &Kw[frow * KSTR];
            kr0[kp0] = packh(ka.x, ka.y);
            kr0[kp1] = packh(ka.z, ka.w);
            uint32_t* kr1 = &Kw[(frow + 16) * KSTR];
            kr1[kp0] = packh(kb4.x, kb4.y);
            kr1[kp1] = packh(kb4.z, kb4.w);

            uint32_t* vhp = &Vh[vp * AVSTR + vcg];
            vhp[0] = packh(va0.x, va1.x);
            vhp[1] = packh(va0.y, va1.y);
            vhp[2] = packh(va0.z, va1.z);
            vhp[3] = packh(va0.w, va1.w);

            if (tid < 32) Bs[tid] = g_bias[b * T_ + s0 + tid];
        }
        __syncthreads();

        if (s0 + 32 < T_) {
            ka  = *(const float4*)(kRow + (size_t)(s0 + 32) * D_);
            kb4 = *(const float4*)(kRow + (size_t)(s0 + 48) * D_);
            va0 = *(const float4*)(vRow0 + (size_t)(s0 + 32) * D_);
            va1 = *(const float4*)(vRow1 + (size_t)(s0 + 32) * D_);
        }

        // ---- S = (Q*scale*log2e) K^T (fp16 x1, k16; LDS.64 B-frags) ----
        float sv[4][4];
#pragma unroll
        for (int nt = 0; nt < 4; nt++)
#pragma unroll
            for (int i = 0; i < 4; i++) sv[nt][i] = 0.f;
#pragma unroll
        for (int ks = 0; ks < 4; ks++) {
#pragma unroll
            for (int nt = 0; nt < 4; nt++) {
                uint2 bb = *(const uint2*)&Kw[(nt * 8 + gid) * KSTR + ks * 8 + 2 * tig];
                uint32_t bh[2] = { bb.x, bb.y };
                mma_f16(sv[nt], Qr[ks], bh);
            }
        }

        // ---- bias add, online softmax (exp2 domain) ----
#pragma unroll
        for (int nt = 0; nt < 4; nt++) {
            int c0 = nt * 8 + 2 * tig;
            float bb0 = Bs[c0], bb1 = Bs[c0 + 1];
            sv[nt][0] += bb0;
            sv[nt][1] += bb1;
            sv[nt][2] += bb0;
            sv[nt][3] += bb1;
        }
        float mx0 = fmaxf(fmaxf(sv[0][0], sv[0][1]), fmaxf(sv[1][0], sv[1][1]));
        mx0 = fmaxf(mx0, fmaxf(fmaxf(sv[2][0], sv[2][1]), fmaxf(sv[3][0], sv[3][1])));
        float mx1 = fmaxf(fmaxf(sv[0][2], sv[0][3]), fmaxf(sv[1][2], sv[1][3]));
        mx1 = fmaxf(mx1, fmaxf(fmaxf(sv[2][2], sv[2][3]), fmaxf(sv[3][2], sv[3][3])));
        mx0 = fmaxf(mx0, __shfl_xor_sync(0xffffffffu, mx0, 1));
        mx0 = fmaxf(mx0, __shfl_xor_sync(0xffffffffu, mx0, 2));
        mx1 = fmaxf(mx1, __shfl_xor_sync(0xffffffffu, mx1, 1));
        mx1 = fmaxf(mx1, __shfl_xor_sync(0xffffffffu, mx1, 2));

        float m0n = fmaxf(m0, mx0), m1n = fmaxf(m1, mx1);
        float c0f = exp2f(m0 - m0n), c1f = exp2f(m1 - m1n);
        m0 = m0n; m1 = m1n;

        float rs0 = 0.f, rs1 = 0.f;
#pragma unroll
        for (int nt = 0; nt < 4; nt++) {
            float p0 = exp2f(sv[nt][0] - m0n);
            float p1 = exp2f(sv[nt][1] - m0n);
            float p2 = exp2f(sv[nt][2] - m1n);
            float p3 = exp2f(sv[nt][3] - m1n);
            rs0 += p0 + p1; rs1 += p2 + p3;
            sv[nt][0] = p0; sv[nt][1] = p1;
            sv[nt][2] = p2; sv[nt][3] = p3;
        }
        rs0 += __shfl_xor_sync(0xffffffffu, rs0, 1);
        rs0 += __shfl_xor_sync(0xffffffffu, rs0, 2);
        rs1 += __shfl_xor_sync(0xffffffffu, rs1, 1);
        rs1 += __shfl_xor_sync(0xffffffffu, rs1, 2);
        l0 = l0 * c0f + rs0;
        l1 = l1 * c1f + rs1;
#pragma unroll
        for (int nt = 0; nt < 8; nt++) {
            oacc[nt][0] *= c0f; oacc[nt][1] *= c0f;
            oacc[nt][2] *= c1f; oacc[nt][3] *= c1f;
        }

        // ---- O += P V (fp16 x1; P A-frags built from S C-frags in registers) ----
#pragma unroll
        for (int kk = 0; kk < 2; kk++) {
            uint32_t ah[4];
            ah[0] = packh(sv[2 * kk][0],     sv[2 * kk][1]);
            ah[1] = packh(sv[2 * kk][2],     sv[2 * kk][3]);
            ah[2] = packh(sv[2 * kk + 1][0], sv[2 * kk + 1][1]);
            ah[3] = packh(sv[2 * kk + 1][2], sv[2 * kk + 1][3]);
#pragma unroll
            for (int nt = 0; nt < 8; nt++) {
                uint32_t bh[2];
                bh[0] = Vh[(kk * 8 + tig) * AVSTR + nt * 8 + gid];
                bh[1] = Vh[(kk * 8 + tig + 4) * AVSTR + nt * 8 + gid];
                mma_f16(oacc[nt], ah, bh);
            }
        }
    }

    float inv0 = 1.f / l0, inv1 = 1.f / l1;
    const int gr0 = t0 + wid * 16 + gid;
    float* o0 = CTX + ((size_t)(b * T_) + gr0) * D_ + h * DK_;
    float* o1 = o0 + 8 * D_;
#pragma unroll
    for (int nt = 0; nt < 8; nt++) {
        int c = nt * 8 + 2 * tig;
        *(float2*)(o0 + c) = make_float2(oacc[nt][0] * inv0, oacc[nt][1] * inv0);
        *(float2*)(o1 + c) = make_float2(oacc[nt][2] * inv1, oacc[nt][3] * inv1);
    }
}

// ---------------- launch ----------------
extern "C" void kernel_launch(void* const* d_in, const int* in_sizes, int n_in,
                              void* d_out, int out_size)
{
    const float* query = (const float*)d_in[0];
    const float* key   = (const float*)d_in[1];
    const float* value = (const float*)d_in[2];
    const void*  mask  = d_in[3];
    const float* Wq = (const float*)d_in[4];  const float* bq = (const float*)d_in[5];
    const float* Wk = (const float*)d_in[6];  const float* bk = (const float*)d_in[7];
    const float* Wv = (const float*)d_in[8];  const float* bv = (const float*)d_in[9];
    const float* Wo = (const float*)d_in[10]; const float* bo = (const float*)d_in[11];

    float *Qb, *Kb, *Vb, *Cb;
    cudaGetSymbolAddress((void**)&Qb, g_Q);
    cudaGetSymbolAddress((void**)&Kb, g_K);
    cudaGetSymbolAddress((void**)&Vb, g_V);
    cudaGetSymbolAddress((void**)&Cb, g_CTX);

    detect_mask_kernel<<<1, 256>>>((const unsigned int*)mask);
    build_bias_kernel<<<(M_ + 255) / 256, 256>>>(mask);

    GemmBatch gqkv;
    gqkv.A[0] = query; gqkv.A[1] = key; gqkv.A[2] = value;
    gqkv.W[0] = Wq;    gqkv.W[1] = Wk;  gqkv.W[2] = Wv;
    gqkv.bias[0] = bq; gqkv.bias[1] = bk; gqkv.bias[2] = bv;
    gqkv.C[0] = Qb;    gqkv.C[1] = Kb;  gqkv.C[2] = Vb;
    gemm_f16x2_kernel<<<dim3(D_ / 128, M_ / 128, 3), 256>>>(gqkv);

    attn_mma_kernel<<<dim3(T_ / 128, H_, B_), 256>>>(Qb, Kb, Vb, Cb);

    GemmBatch go;
    go.A[0] = Cb; go.A[1] = Cb; go.A[2] = Cb;
    go.W[0] = Wo; go.W[1] = Wo; go.W[2] = Wo;
    go.bias[0] = bo; go.bias[1] = bo; go.bias[2] = bo;
    go.C[0] = (float*)d_out; go.C[1] = (float*)d_out; go.C[2] = (float*)d_out;
    gemm_f16x2_kernel<<<dim3(D_ / 128, M_ / 128, 1), 256>>>(go);
}